// round 1
// baseline (speedup 1.0000x reference)
#include <cuda_runtime.h>
#include <math.h>

#define NN   10000
#define EE   160000
#define CIN_ 32
#define HH   64
#define TT   12
#define OUTC 12
#define FEAT 768   // HH*TT

// ---------------- scratch (device globals; no allocation) ----------------
__device__ float g_bufA[NN * FEAT];
__device__ float g_bufB[NN * FEAT];
__device__ float g_deg[NN];
__device__ float g_dis[NN];
__device__ int   g_cnt[NN];
__device__ int   g_rowptr[NN + 1];
__device__ int   g_srcs[EE];
__device__ float g_coef[EE];

// ---------------- CSR build ----------------
__global__ void zero_kernel() {
    int i = blockIdx.x * blockDim.x + threadIdx.x;
    if (i < NN) { g_deg[i] = 0.f; g_cnt[i] = 0; }
}

__global__ void hist_kernel(const int* __restrict__ ei, const float* __restrict__ ew) {
    int e = blockIdx.x * blockDim.x + threadIdx.x;
    if (e < EE) {
        int d = ei[EE + e];
        atomicAdd(&g_deg[d], ew[e]);
        atomicAdd(&g_cnt[d], 1);
    }
}

// single block: exclusive scan of counts -> rowptr, dis = rsqrt(deg+1), reset cnt
__global__ void scan_kernel() {
    __shared__ int sd[1024];
    int tid = threadIdx.x;
    int offset = 0;
    for (int base = 0; base < NN; base += 1024) {
        int i = base + tid;
        int v = (i < NN) ? g_cnt[i] : 0;
        if (i < NN) { g_dis[i] = rsqrtf(g_deg[i] + 1.0f); g_cnt[i] = 0; }
        sd[tid] = v;
        __syncthreads();
        for (int s = 1; s < 1024; s <<= 1) {
            int t = (tid >= s) ? sd[tid - s] : 0;
            __syncthreads();
            sd[tid] += t;
            __syncthreads();
        }
        if (i < NN) g_rowptr[i] = offset + sd[tid] - v;
        offset += sd[1023];
        __syncthreads();
    }
    if (tid == 0) g_rowptr[NN] = offset;
}

__global__ void scatter_kernel(const int* __restrict__ ei, const float* __restrict__ ew) {
    int e = blockIdx.x * blockDim.x + threadIdx.x;
    if (e < EE) {
        int d = ei[EE + e];
        int s = ei[e];
        int pos = g_rowptr[d] + atomicAdd(&g_cnt[d], 1);
        g_srcs[pos] = s;
        g_coef[pos] = g_dis[s] * ew[e] * g_dis[d];
    }
}

// ---------------- gated temporal conv (K=3, pad=1), in (N,C,12) -> out (N,64,12) ----
template <int C>
__global__ void tconv_kernel(const float* __restrict__ x, const float* __restrict__ w,
                             const float* __restrict__ bias, float* __restrict__ out) {
    extern __shared__ float sm[];
    float* wPs = sm;                 // [c*3+k][64]
    float* wQs = sm + C * 192;
    float* xs  = sm + 2 * C * 192;   // 4 nodes, stride C*12+8
    const int tid = threadIdx.x;     // 256
    const int XST = C * 12 + 8;

    for (int gi = tid; gi < 128 * C * 3; gi += 256) {
        int o = gi / (C * 3);
        int rem = gi - o * (C * 3);
        int c = rem / 3, k = rem - c * 3;
        float v = w[gi];
        ((o < 64) ? wPs : wQs)[(c * 3 + k) * 64 + (o & 63)] = v;
    }
    int n0 = blockIdx.x * 4;
    for (int gi = tid; gi < C * 12; gi += 256) {       // 4 nodes * C*3 float4
        int node = gi / (C * 3), j = gi - node * (C * 3);
        ((float4*)(xs + node * XST))[j] =
            ((const float4*)(x + (size_t)(n0 + node) * C * 12))[j];
    }
    __syncthreads();

    int node = tid >> 6, h = tid & 63;
    const float* xb = xs + node * XST;
    float P[12], Q[12];
#pragma unroll
    for (int t = 0; t < 12; t++) { P[t] = 0.f; Q[t] = 0.f; }

    for (int c = 0; c < C; c++) {
        float4 a0 = ((const float4*)(xb + c * 12))[0];
        float4 a1 = ((const float4*)(xb + c * 12))[1];
        float4 a2 = ((const float4*)(xb + c * 12))[2];
        float xr[12] = {a0.x, a0.y, a0.z, a0.w, a1.x, a1.y, a1.z, a1.w,
                        a2.x, a2.y, a2.z, a2.w};
        const float* wpb = wPs + c * 192 + h;
        const float* wqb = wQs + c * 192 + h;
        float wp0 = wpb[0], wp1 = wpb[64], wp2 = wpb[128];
        float wq0 = wqb[0], wq1 = wqb[64], wq2 = wqb[128];
#pragma unroll
        for (int t = 0; t < 12; t++) { P[t] += wp1 * xr[t]; Q[t] += wq1 * xr[t]; }
#pragma unroll
        for (int t = 1; t < 12; t++) { P[t] += wp0 * xr[t - 1]; Q[t] += wq0 * xr[t - 1]; }
#pragma unroll
        for (int t = 0; t < 11; t++) { P[t] += wp2 * xr[t + 1]; Q[t] += wq2 * xr[t + 1]; }
    }
    float bP = bias[h], bQ = bias[h + 64];
    float r[12];
#pragma unroll
    for (int t = 0; t < 12; t++) {
        float q = Q[t] + bQ;
        r[t] = (P[t] + bP) * (1.f / (1.f + __expf(-q)));
    }
    float* ob = out + (size_t)(n0 + node) * FEAT + h * 12;
    ((float4*)ob)[0] = make_float4(r[0], r[1], r[2], r[3]);
    ((float4*)ob)[1] = make_float4(r[4], r[5], r[6], r[7]);
    ((float4*)ob)[2] = make_float4(r[8], r[9], r[10], r[11]);
}

// ---------------- GCN aggregation (CSR gather), in -> out ----------------
__global__ void gcn_agg_kernel(const float* __restrict__ in, float* __restrict__ out) {
    int n = blockIdx.x;
    int tid = threadIdx.x;   // 192, one float4 each (768 floats)
    float d = g_dis[n];
    float d2 = d * d;
    float4 acc = ((const float4*)(in + (size_t)n * FEAT))[tid];
    acc.x *= d2; acc.y *= d2; acc.z *= d2; acc.w *= d2;
    int e = g_rowptr[n], e1 = g_rowptr[n + 1];
    for (; e < e1; e++) {
        int s = g_srcs[e];
        float c = g_coef[e];
        float4 v = ((const float4*)(in + (size_t)s * FEAT))[tid];
        acc.x += c * v.x; acc.y += c * v.y; acc.z += c * v.z; acc.w += c * v.w;
    }
    ((float4*)(out + (size_t)n * FEAT))[tid] = acc;
}

// ---------------- GCN transform + bias + relu (in-place per node) ----------------
__global__ void gcn_apply_kernel(float* __restrict__ io, const float* __restrict__ W,
                                 const float* __restrict__ b) {
    __shared__ float Ws[4096];        // [c][o]
    __shared__ float xs[4 * 776];
    int tid = threadIdx.x;            // 256
    for (int gi = tid; gi < 4096; gi += 256) {
        int o = gi >> 6, c = gi & 63;
        Ws[c * 64 + o] = W[gi];
    }
    int n0 = blockIdx.x * 4;
    for (int gi = tid; gi < 768; gi += 256) {    // 4 nodes * 192 float4
        int node = gi / 192, j = gi - node * 192;
        ((float4*)(xs + node * 776))[j] =
            ((const float4*)(io + (size_t)(n0 + node) * FEAT))[j];
    }
    __syncthreads();

    int node = tid >> 6, o = tid & 63;
    const float* xb = xs + node * 776;
    float acc[12];
#pragma unroll
    for (int t = 0; t < 12; t++) acc[t] = 0.f;
    for (int c = 0; c < 64; c++) {
        float4 a0 = ((const float4*)(xb + c * 12))[0];
        float4 a1 = ((const float4*)(xb + c * 12))[1];
        float4 a2 = ((const float4*)(xb + c * 12))[2];
        float wv = Ws[c * 64 + o];
        acc[0] += wv * a0.x; acc[1] += wv * a0.y; acc[2] += wv * a0.z; acc[3] += wv * a0.w;
        acc[4] += wv * a1.x; acc[5] += wv * a1.y; acc[6] += wv * a1.z; acc[7] += wv * a1.w;
        acc[8] += wv * a2.x; acc[9] += wv * a2.y; acc[10] += wv * a2.z; acc[11] += wv * a2.w;
    }
    float bv = b[o];
    float r[12];
#pragma unroll
    for (int t = 0; t < 12; t++) r[t] = fmaxf(acc[t] + bv, 0.f);
    float* ob = io + (size_t)(n0 + node) * FEAT + o * 12;
    ((float4*)ob)[0] = make_float4(r[0], r[1], r[2], r[3]);
    ((float4*)ob)[1] = make_float4(r[4], r[5], r[6], r[7]);
    ((float4*)ob)[2] = make_float4(r[8], r[9], r[10], r[11]);
}

// ---------------- final conv: dot over (64,12), out (N,12) ----------------
__global__ void fin_kernel(const float* __restrict__ in, const float* __restrict__ w,
                           const float* __restrict__ b, float* __restrict__ out) {
    extern __shared__ float sm[];
    float* ws = sm;             // 12 rows, stride 772
    float* xs = sm + 12 * 772;  // 16 nodes, stride 772
    int tid = threadIdx.x;      // 192
    for (int gi = tid; gi < 12 * 192; gi += 192) {
        int o = gi / 192, j = gi - o * 192;
        ((float4*)(ws + o * 772))[j] = ((const float4*)(w + o * FEAT))[j];
    }
    int n0 = blockIdx.x * 16;
    for (int gi = tid; gi < 16 * 192; gi += 192) {
        int node = gi / 192, j = gi - node * 192;
        ((float4*)(xs + node * 772))[j] =
            ((const float4*)(in + (size_t)(n0 + node) * FEAT))[j];
    }
    __syncthreads();
    int node = tid / 12, o = tid - node * 12;
    const float* wr = ws + o * 772;
    const float* xr = xs + node * 772;
    float acc = 0.f;
#pragma unroll 4
    for (int j = 0; j < 192; j++) {
        float4 a = ((const float4*)wr)[j];
        float4 v = ((const float4*)xr)[j];
        acc += a.x * v.x + a.y * v.y + a.z * v.z + a.w * v.w;
    }
    out[(size_t)(n0 + node) * OUTC + o] = acc + b[o];
}

// ---------------- launch ----------------
extern "C" void kernel_launch(void* const* d_in, const int* in_sizes, int n_in,
                              void* d_out, int out_size) {
    const float* x      = (const float*)d_in[0];
    const int*   ei     = (const int*)d_in[1];
    const float* ew     = (const float*)d_in[2];
    const float* tc1a_w = (const float*)d_in[3];
    const float* tc1a_b = (const float*)d_in[4];
    const float* gc1_w  = (const float*)d_in[5];
    const float* gc1_b  = (const float*)d_in[6];
    const float* tc1b_w = (const float*)d_in[7];
    const float* tc1b_b = (const float*)d_in[8];
    const float* tc2a_w = (const float*)d_in[9];
    const float* tc2a_b = (const float*)d_in[10];
    const float* gc2_w  = (const float*)d_in[11];
    const float* gc2_b  = (const float*)d_in[12];
    const float* tc2b_w = (const float*)d_in[13];
    const float* tc2b_b = (const float*)d_in[14];
    const float* fin_w  = (const float*)d_in[15];
    const float* fin_b  = (const float*)d_in[16];
    float* out = (float*)d_out;

    float *pA, *pB;
    cudaGetSymbolAddress((void**)&pA, g_bufA);
    cudaGetSymbolAddress((void**)&pB, g_bufB);

    const int smem32 = (2 * 32 * 192 + 4 * (32 * 12 + 8)) * 4;   // 55424
    const int smem64 = (2 * 64 * 192 + 4 * (64 * 12 + 8)) * 4;   // 110720
    const int smemF  = (12 + 16) * 772 * 4;                      // 86464
    cudaFuncSetAttribute(tconv_kernel<32>, cudaFuncAttributeMaxDynamicSharedMemorySize, smem32);
    cudaFuncSetAttribute(tconv_kernel<64>, cudaFuncAttributeMaxDynamicSharedMemorySize, smem64);
    cudaFuncSetAttribute(fin_kernel, cudaFuncAttributeMaxDynamicSharedMemorySize, smemF);

    // CSR build (per launch, deterministic work)
    zero_kernel<<<(NN + 255) / 256, 256>>>();
    hist_kernel<<<(EE + 255) / 256, 256>>>(ei, ew);
    scan_kernel<<<1, 1024>>>();
    scatter_kernel<<<(EE + 255) / 256, 256>>>(ei, ew);

    // tc1a: x (N,32,12) -> bufA (N,64,12)
    tconv_kernel<32><<<NN / 4, 256, smem32>>>(x, tc1a_w, tc1a_b, pA);
    // gcn1: aggregate bufA -> bufB, then W/b/relu in place
    gcn_agg_kernel<<<NN, 192>>>(pA, pB);
    gcn_apply_kernel<<<NN / 4, 256>>>(pB, gc1_w, gc1_b);
    // tc1b: bufB -> bufA
    tconv_kernel<64><<<NN / 4, 256, smem64>>>(pB, tc1b_w, tc1b_b, pA);
    // tc2a: bufA -> bufB
    tconv_kernel<64><<<NN / 4, 256, smem64>>>(pA, tc2a_w, tc2a_b, pB);
    // gcn2: aggregate bufB -> bufA, transform in place
    gcn_agg_kernel<<<NN, 192>>>(pB, pA);
    gcn_apply_kernel<<<NN / 4, 256>>>(pA, gc2_w, gc2_b);
    // tc2b: bufA -> bufB
    tconv_kernel<64><<<NN / 4, 256, smem64>>>(pA, tc2b_w, tc2b_b, pB);
    // fin: bufB -> out (N,12)
    fin_kernel<<<NN / 16, 192, smemF>>>(pB, fin_w, fin_b, out);
}

// round 2
// speedup vs baseline: 1.3817x; 1.3817x over previous
#include <cuda_runtime.h>
#include <math.h>

#define NN   10000
#define EE   160000
#define FEAT 768   // 64*12

typedef unsigned long long ull;

// ---------------- scratch (device globals; no allocation) ----------------
__device__ float g_bufA[NN * FEAT];
__device__ float g_bufB[NN * FEAT];
__device__ float g_deg[NN];
__device__ float g_dis[NN];
__device__ int   g_cnt[NN];
__device__ int   g_rowptr[NN + 1];
__device__ ull   g_edge[EE];     // packed: low 32 = src, high 32 = coef bits

// ---------------- f32x2 helpers ----------------
__device__ __forceinline__ void ffma2(ull& d, ull a, ull b) {
    asm("fma.rn.f32x2 %0, %1, %2, %0;" : "+l"(d) : "l"(a), "l"(b));
}
__device__ __forceinline__ float2 upk(ull v) {
    float2 r; asm("mov.b64 {%0, %1}, %2;" : "=f"(r.x), "=f"(r.y) : "l"(v));
    return r;
}

// ---------------- CSR build ----------------
__global__ void zero_kernel() {
    int i = blockIdx.x * blockDim.x + threadIdx.x;
    if (i < NN) { g_deg[i] = 0.f; g_cnt[i] = 0; }
}

__global__ void hist_kernel(const int* __restrict__ ei, const float* __restrict__ ew) {
    int e = blockIdx.x * blockDim.x + threadIdx.x;
    if (e < EE) {
        int d = ei[EE + e];
        atomicAdd(&g_deg[d], ew[e]);
        atomicAdd(&g_cnt[d], 1);
    }
}

__global__ void scan_kernel() {
    __shared__ int sd[1024];
    int tid = threadIdx.x;
    int offset = 0;
    for (int base = 0; base < NN; base += 1024) {
        int i = base + tid;
        int v = (i < NN) ? g_cnt[i] : 0;
        if (i < NN) { g_dis[i] = rsqrtf(g_deg[i] + 1.0f); g_cnt[i] = 0; }
        sd[tid] = v;
        __syncthreads();
        for (int s = 1; s < 1024; s <<= 1) {
            int t = (tid >= s) ? sd[tid - s] : 0;
            __syncthreads();
            sd[tid] += t;
            __syncthreads();
        }
        if (i < NN) g_rowptr[i] = offset + sd[tid] - v;
        offset += sd[1023];
        __syncthreads();
    }
    if (tid == 0) g_rowptr[NN] = offset;
}

__global__ void scatter_kernel(const int* __restrict__ ei, const float* __restrict__ ew) {
    int e = blockIdx.x * blockDim.x + threadIdx.x;
    if (e < EE) {
        int d = ei[EE + e];
        int s = ei[e];
        int pos = g_rowptr[d] + atomicAdd(&g_cnt[d], 1);
        float coef = g_dis[s] * ew[e] * g_dis[d];
        g_edge[pos] = ((ull)__float_as_uint(coef) << 32) | (unsigned)s;
    }
}

// ---------------- gated temporal conv via f32x2 ----------------
template <int C>
__global__ void __launch_bounds__(512, 1)
tconv_kernel(const float* __restrict__ x, const float* __restrict__ w,
             const float* __restrict__ bias, float* __restrict__ out) {
    extern __shared__ ull smu[];
    ull*   wS = smu;                       // [(c*3+k)*128 + o], dup pair
    float* xs = (float*)(smu + C * 3 * 128);
    const int XST = C * 12 + 8;
    const int tid = threadIdx.x;

    for (int gi = tid; gi < 128 * C * 3; gi += 512) {
        int o = gi / (C * 3);
        int rem = gi - o * (C * 3);
        int c = rem / 3, k = rem - c * 3;
        unsigned u = __float_as_uint(w[gi]);
        wS[(c * 3 + k) * 128 + o] = (ull)u | ((ull)u << 32);
    }
    int n0 = blockIdx.x * 8;
    for (int gi = tid; gi < 8 * C * 3; gi += 512) {
        int node = gi / (C * 3), j = gi - node * (C * 3);
        ((float4*)(xs + node * XST))[j] =
            ((const float4*)(x + (size_t)(n0 + node) * C * 12))[j];
    }
    __syncthreads();

    int node = tid >> 6, h = tid & 63;
    const float* xb = xs + node * XST;
    ull aP0[6], aP1[6], aP2[6], aQ0[6], aQ1[6], aQ2[6];
#pragma unroll
    for (int j = 0; j < 6; j++) {
        aP0[j] = aP1[j] = aP2[j] = 0ull;
        aQ0[j] = aQ1[j] = aQ2[j] = 0ull;
    }

    for (int c = 0; c < C; c++) {
        const ulonglong2* xp = (const ulonglong2*)(xb + c * 12);
        ulonglong2 u0 = xp[0], u1 = xp[1], u2 = xp[2];
        ull xv[6] = {u0.x, u0.y, u1.x, u1.y, u2.x, u2.y};
        const ull* wb = wS + c * 3 * 128;
        ull wp0 = wb[h],      wp1 = wb[128 + h], wp2 = wb[256 + h];
        ull wq0 = wb[64 + h], wq1 = wb[192 + h], wq2 = wb[320 + h];
#pragma unroll
        for (int j = 0; j < 6; j++) {
            ffma2(aP0[j], wp0, xv[j]);
            ffma2(aP1[j], wp1, xv[j]);
            ffma2(aP2[j], wp2, xv[j]);
            ffma2(aQ0[j], wq0, xv[j]);
            ffma2(aQ1[j], wq1, xv[j]);
            ffma2(aQ2[j], wq2, xv[j]);
        }
    }

    float A0[12], A1[12], A2[12], B0[12], B1[12], B2[12];
#pragma unroll
    for (int j = 0; j < 6; j++) {
        float2 f;
        f = upk(aP0[j]); A0[2 * j] = f.x; A0[2 * j + 1] = f.y;
        f = upk(aP1[j]); A1[2 * j] = f.x; A1[2 * j + 1] = f.y;
        f = upk(aP2[j]); A2[2 * j] = f.x; A2[2 * j + 1] = f.y;
        f = upk(aQ0[j]); B0[2 * j] = f.x; B0[2 * j + 1] = f.y;
        f = upk(aQ1[j]); B1[2 * j] = f.x; B1[2 * j + 1] = f.y;
        f = upk(aQ2[j]); B2[2 * j] = f.x; B2[2 * j + 1] = f.y;
    }
    float bP = bias[h], bQ = bias[64 + h];
    float r[12];
#pragma unroll
    for (int t = 0; t < 12; t++) {
        float P = A1[t] + bP;
        float Q = B1[t] + bQ;
        if (t > 0)  { P += A0[t - 1]; Q += B0[t - 1]; }
        if (t < 11) { P += A2[t + 1]; Q += B2[t + 1]; }
        r[t] = P * (1.f / (1.f + __expf(-Q)));
    }
    float* ob = out + (size_t)(n0 + node) * FEAT + h * 12;
    ((float4*)ob)[0] = make_float4(r[0], r[1], r[2], r[3]);
    ((float4*)ob)[1] = make_float4(r[4], r[5], r[6], r[7]);
    ((float4*)ob)[2] = make_float4(r[8], r[9], r[10], r[11]);
}

// ---------------- fused GCN: CSR gather-aggregate + W + bias + relu --------
__global__ void __launch_bounds__(192)
gcn_fused_kernel(const float* __restrict__ in, float* __restrict__ out,
                 const float* __restrict__ W, const float* __restrict__ bias) {
    __shared__ __align__(16) float xs[768];
    __shared__ float Ws[64 * 65];          // transposed [c][o], pad 65
    int n = blockIdx.x, tid = threadIdx.x;

    for (int gi = tid; gi < 4096; gi += 192) {
        int o = gi >> 6, c = gi & 63;
        Ws[c * 65 + o] = W[gi];
    }

    float d = g_dis[n];
    float d2 = d * d;
    float4 acc = ((const float4*)(in + (size_t)n * FEAT))[tid];
    acc.x *= d2; acc.y *= d2; acc.z *= d2; acc.w *= d2;

    int e = g_rowptr[n], e1 = g_rowptr[n + 1];
    for (; e + 4 <= e1; e += 4) {
        ull p0 = g_edge[e], p1 = g_edge[e + 1], p2 = g_edge[e + 2], p3 = g_edge[e + 3];
        int s0 = (int)(unsigned)p0, s1 = (int)(unsigned)p1;
        int s2 = (int)(unsigned)p2, s3 = (int)(unsigned)p3;
        float c0 = __uint_as_float((unsigned)(p0 >> 32));
        float c1 = __uint_as_float((unsigned)(p1 >> 32));
        float c2 = __uint_as_float((unsigned)(p2 >> 32));
        float c3 = __uint_as_float((unsigned)(p3 >> 32));
        float4 v0 = ((const float4*)(in + (size_t)s0 * FEAT))[tid];
        float4 v1 = ((const float4*)(in + (size_t)s1 * FEAT))[tid];
        float4 v2 = ((const float4*)(in + (size_t)s2 * FEAT))[tid];
        float4 v3 = ((const float4*)(in + (size_t)s3 * FEAT))[tid];
        acc.x += c0 * v0.x + c1 * v1.x + c2 * v2.x + c3 * v3.x;
        acc.y += c0 * v0.y + c1 * v1.y + c2 * v2.y + c3 * v3.y;
        acc.z += c0 * v0.z + c1 * v1.z + c2 * v2.z + c3 * v3.z;
        acc.w += c0 * v0.w + c1 * v1.w + c2 * v2.w + c3 * v3.w;
    }
    for (; e < e1; e++) {
        ull p = g_edge[e];
        int s = (int)(unsigned)p;
        float cf = __uint_as_float((unsigned)(p >> 32));
        float4 v = ((const float4*)(in + (size_t)s * FEAT))[tid];
        acc.x += cf * v.x; acc.y += cf * v.y; acc.z += cf * v.z; acc.w += cf * v.w;
    }
    ((float4*)xs)[tid] = acc;
    __syncthreads();

    int o = tid & 63, tg = tid >> 6;    // tg 0..2, 4 t's each
    float4 r = make_float4(0.f, 0.f, 0.f, 0.f);
    const float* xp = xs + tg * 4;
#pragma unroll 8
    for (int c = 0; c < 64; c++) {
        float wv = Ws[c * 65 + o];
        float4 xv = *(const float4*)(xp + c * 12);
        r.x += wv * xv.x; r.y += wv * xv.y; r.z += wv * xv.z; r.w += wv * xv.w;
    }
    float bv = bias[o];
    float4 res = make_float4(fmaxf(r.x + bv, 0.f), fmaxf(r.y + bv, 0.f),
                             fmaxf(r.z + bv, 0.f), fmaxf(r.w + bv, 0.f));
    *(float4*)(out + (size_t)n * FEAT + o * 12 + tg * 4) = res;
}

// ---------------- final conv: dot over (64,12), out (N,12) ----------------
__global__ void fin_kernel(const float* __restrict__ in, const float* __restrict__ w,
                           const float* __restrict__ b, float* __restrict__ out) {
    extern __shared__ float sm[];
    float* ws = sm;             // 12 rows, stride 772
    float* xs = sm + 12 * 772;  // 16 nodes, stride 772
    int tid = threadIdx.x;      // 192
    for (int gi = tid; gi < 12 * 192; gi += 192) {
        int o = gi / 192, j = gi - o * 192;
        ((float4*)(ws + o * 772))[j] = ((const float4*)(w + o * FEAT))[j];
    }
    int n0 = blockIdx.x * 16;
    for (int gi = tid; gi < 16 * 192; gi += 192) {
        int node = gi / 192, j = gi - node * 192;
        ((float4*)(xs + node * 772))[j] =
            ((const float4*)(in + (size_t)(n0 + node) * FEAT))[j];
    }
    __syncthreads();
    int node = tid / 12, o = tid - node * 12;
    const float* wr = ws + o * 772;
    const float* xr = xs + node * 772;
    float acc = 0.f;
#pragma unroll 4
    for (int j = 0; j < 192; j++) {
        float4 a = ((const float4*)wr)[j];
        float4 v = ((const float4*)xr)[j];
        acc += a.x * v.x + a.y * v.y + a.z * v.z + a.w * v.w;
    }
    out[(size_t)(n0 + node) * 12 + o] = acc + b[o];
}

// ---------------- launch ----------------
extern "C" void kernel_launch(void* const* d_in, const int* in_sizes, int n_in,
                              void* d_out, int out_size) {
    const float* x      = (const float*)d_in[0];
    const int*   ei     = (const int*)d_in[1];
    const float* ew     = (const float*)d_in[2];
    const float* tc1a_w = (const float*)d_in[3];
    const float* tc1a_b = (const float*)d_in[4];
    const float* gc1_w  = (const float*)d_in[5];
    const float* gc1_b  = (const float*)d_in[6];
    const float* tc1b_w = (const float*)d_in[7];
    const float* tc1b_b = (const float*)d_in[8];
    const float* tc2a_w = (const float*)d_in[9];
    const float* tc2a_b = (const float*)d_in[10];
    const float* gc2_w  = (const float*)d_in[11];
    const float* gc2_b  = (const float*)d_in[12];
    const float* tc2b_w = (const float*)d_in[13];
    const float* tc2b_b = (const float*)d_in[14];
    const float* fin_w  = (const float*)d_in[15];
    const float* fin_b  = (const float*)d_in[16];
    float* out = (float*)d_out;

    float *pA, *pB;
    cudaGetSymbolAddress((void**)&pA, g_bufA);
    cudaGetSymbolAddress((void**)&pB, g_bufB);

    const int smem32 = 32 * 3 * 128 * 8 + 8 * (32 * 12 + 8) * 4;   // 110848
    const int smem64 = 64 * 3 * 128 * 8 + 8 * (64 * 12 + 8) * 4;   // 221440
    const int smemF  = (12 + 16) * 772 * 4;                        // 86464
    cudaFuncSetAttribute(tconv_kernel<32>, cudaFuncAttributeMaxDynamicSharedMemorySize, smem32);
    cudaFuncSetAttribute(tconv_kernel<64>, cudaFuncAttributeMaxDynamicSharedMemorySize, smem64);
    cudaFuncSetAttribute(fin_kernel, cudaFuncAttributeMaxDynamicSharedMemorySize, smemF);

    // CSR build
    zero_kernel<<<(NN + 255) / 256, 256>>>();
    hist_kernel<<<(EE + 255) / 256, 256>>>(ei, ew);
    scan_kernel<<<1, 1024>>>();
    scatter_kernel<<<(EE + 255) / 256, 256>>>(ei, ew);

    // tc1a: x -> A
    tconv_kernel<32><<<NN / 8, 512, smem32>>>(x, tc1a_w, tc1a_b, pA);
    // gcn1 (agg + W + relu): A -> B
    gcn_fused_kernel<<<NN, 192>>>(pA, pB, gc1_w, gc1_b);
    // tc1b: B -> A
    tconv_kernel<64><<<NN / 8, 512, smem64>>>(pB, tc1b_w, tc1b_b, pA);
    // tc2a: A -> B
    tconv_kernel<64><<<NN / 8, 512, smem64>>>(pA, tc2a_w, tc2a_b, pB);
    // gcn2: B -> A
    gcn_fused_kernel<<<NN, 192>>>(pB, pA, gc2_w, gc2_b);
    // tc2b: A -> B
    tconv_kernel<64><<<NN / 8, 512, smem64>>>(pA, tc2b_w, tc2b_b, pB);
    // fin: B -> out
    fin_kernel<<<NN / 16, 192, smemF>>>(pB, fin_w, fin_b, out);
}

// round 4
// speedup vs baseline: 2.4343x; 1.7619x over previous
#include <cuda_runtime.h>
#include <math.h>

#define NN   10000
#define EE   160000
#define FEAT 768   // 64*12

typedef unsigned long long ull;

// ---------------- scratch (device globals; no allocation) ----------------
__device__ float g_bufA[NN * FEAT];
__device__ float g_bufB[NN * FEAT];
__device__ float g_deg[NN];
__device__ float g_dis[NN];
__device__ int   g_cnt[NN];
__device__ int   g_rowptr[NN + 1];
__device__ ull   g_edge[EE];       // low 32 = src, high 32 = coef bits
__device__ ull   g_wpk[43008];     // packed (wp,wq) weights: tc1a@0, tc1b@6144, tc2a@18432, tc2b@30720

// ---------------- f32x2 helpers ----------------
__device__ __forceinline__ void ffma2(ull& d, ull a, ull b) {
    asm("fma.rn.f32x2 %0, %1, %2, %0;" : "+l"(d) : "l"(a), "l"(b));
}
__device__ __forceinline__ float2 upk(ull v) {
    float2 r; asm("mov.b64 {%0, %1}, %2;" : "=f"(r.x), "=f"(r.y) : "l"(v));
    return r;
}
__device__ __forceinline__ ull dup2(float x) {
    unsigned u = __float_as_uint(x);
    ull r; asm("mov.b64 %0, {%1, %1};" : "=l"(r) : "r"(u));
    return r;
}

// ---------------- CSR build ----------------
__global__ void zero_kernel() {
    int i = blockIdx.x * blockDim.x + threadIdx.x;
    if (i < NN) { g_deg[i] = 0.f; g_cnt[i] = 0; }
}

__global__ void hist_kernel(const int* __restrict__ ei, const float* __restrict__ ew) {
    int e = blockIdx.x * blockDim.x + threadIdx.x;
    if (e < EE) {
        int d = ei[EE + e];
        atomicAdd(&g_deg[d], ew[e]);
        atomicAdd(&g_cnt[d], 1);
    }
}

__global__ void scan_kernel() {
    __shared__ int sd[1024];
    int tid = threadIdx.x;
    int offset = 0;
    for (int base = 0; base < NN; base += 1024) {
        int i = base + tid;
        int v = (i < NN) ? g_cnt[i] : 0;
        if (i < NN) { g_dis[i] = rsqrtf(g_deg[i] + 1.0f); g_cnt[i] = 0; }
        sd[tid] = v;
        __syncthreads();
        for (int s = 1; s < 1024; s <<= 1) {
            int t = (tid >= s) ? sd[tid - s] : 0;
            __syncthreads();
            sd[tid] += t;
            __syncthreads();
        }
        if (i < NN) g_rowptr[i] = offset + sd[tid] - v;
        offset += sd[1023];
        __syncthreads();
    }
    if (tid == 0) g_rowptr[NN] = offset;
}

__global__ void scatter_kernel(const int* __restrict__ ei, const float* __restrict__ ew) {
    int e = blockIdx.x * blockDim.x + threadIdx.x;
    if (e < EE) {
        int d = ei[EE + e];
        int s = ei[e];
        int pos = g_rowptr[d] + atomicAdd(&g_cnt[d], 1);
        float coef = g_dis[s] * ew[e] * g_dis[d];
        g_edge[pos] = ((ull)__float_as_uint(coef) << 32) | (unsigned)s;
    }
}

// ---------------- weight pre-pack: w[o][c][k] fp32 -> (wp,wq) pairs --------
// dst[(c*3+k)*64 + h] = { lo: w[h][c][k], hi: w[64+h][c][k] }
__global__ void pack_w_kernel(const float* __restrict__ w, ull* __restrict__ dst, int C) {
    int i = blockIdx.x * 256 + threadIdx.x;
    if (i < 3 * C * 64) {
        int h = i & 63;
        int ck = i >> 6;              // c*3 + k
        float wp = w[(size_t)h * C * 3 + ck];
        float wq = w[(size_t)(64 + h) * C * 3 + ck];
        dst[i] = ((ull)__float_as_uint(wq) << 32) | __float_as_uint(wp);
    }
}

// ---------------- gated temporal conv, (P,Q)-paired f32x2 ----------------
// x: [n][C][12]; out: [n][64][12]; wpk: packed weights
template <int C>
__global__ void __launch_bounds__(256)
tconv_kernel(const float* __restrict__ x, const ull* __restrict__ wpk,
             const float* __restrict__ bias, float* __restrict__ out) {
    extern __shared__ char smc[];
    ull*   wS = (ull*)smc;                     // [(c*3+k)*64 + h]
    float* xs = (float*)(smc + 3 * C * 64 * 8);
    const int XST = C * 12 + 8;
    const int tid = threadIdx.x;

    // stage packed weights (coalesced float4 copy)
    {
        const float4* wsrc = (const float4*)wpk;
        float4* wdst = (float4*)wS;
        for (int i = tid; i < 3 * C * 32; i += 256) wdst[i] = wsrc[i];
    }
    int n0 = blockIdx.x * 4;
    for (int gi = tid; gi < 4 * C * 3; gi += 256) {
        int node = gi / (C * 3), j = gi - node * (C * 3);
        ((float4*)(xs + node * XST))[j] =
            ((const float4*)(x + (size_t)(n0 + node) * C * 12))[j];
    }
    __syncthreads();

    int node = tid >> 6, h = tid & 63;
    const float* xb = xs + node * XST;
    ull acc[12];
#pragma unroll
    for (int t = 0; t < 12; t++) acc[t] = 0ull;

    for (int c = 0; c < C; c++) {
        float4 a0 = ((const float4*)(xb + c * 12))[0];
        float4 a1 = ((const float4*)(xb + c * 12))[1];
        float4 a2 = ((const float4*)(xb + c * 12))[2];
        ull xd[12];
        xd[0] = dup2(a0.x);  xd[1] = dup2(a0.y);  xd[2] = dup2(a0.z);  xd[3] = dup2(a0.w);
        xd[4] = dup2(a1.x);  xd[5] = dup2(a1.y);  xd[6] = dup2(a1.z);  xd[7] = dup2(a1.w);
        xd[8] = dup2(a2.x);  xd[9] = dup2(a2.y);  xd[10] = dup2(a2.z); xd[11] = dup2(a2.w);
        const ull* wb = wS + c * 192;
        ull w0 = wb[h], w1 = wb[64 + h], w2 = wb[128 + h];
        ffma2(acc[0], w1, xd[0]);
        ffma2(acc[0], w2, xd[1]);
#pragma unroll
        for (int t = 1; t < 11; t++) {
            ffma2(acc[t], w0, xd[t - 1]);
            ffma2(acc[t], w1, xd[t]);
            ffma2(acc[t], w2, xd[t + 1]);
        }
        ffma2(acc[11], w0, xd[10]);
        ffma2(acc[11], w1, xd[11]);
    }

    float bP = bias[h], bQ = bias[64 + h];
    float r[12];
#pragma unroll
    for (int t = 0; t < 12; t++) {
        float2 pq = upk(acc[t]);
        float P = pq.x + bP;
        float Q = pq.y + bQ;
        r[t] = P * (1.f / (1.f + __expf(-Q)));
    }
    float* ob = out + (size_t)(n0 + node) * FEAT + h * 12;
    ((float4*)ob)[0] = make_float4(r[0], r[1], r[2], r[3]);
    ((float4*)ob)[1] = make_float4(r[4], r[5], r[6], r[7]);
    ((float4*)ob)[2] = make_float4(r[8], r[9], r[10], r[11]);
}

// ---------------- fused GCN: CSR gather-aggregate + W + bias + relu --------
__global__ void __launch_bounds__(192)
gcn_fused_kernel(const float* __restrict__ in, float* __restrict__ out,
                 const float* __restrict__ W, const float* __restrict__ bias) {
    __shared__ __align__(16) float xs[768];
    __shared__ float Ws[64 * 65];          // transposed [c][o], pad 65
    int n = blockIdx.x, tid = threadIdx.x;

    for (int gi = tid; gi < 4096; gi += 192) {
        int o = gi >> 6, c = gi & 63;
        Ws[c * 65 + o] = W[gi];
    }

    float d = g_dis[n];
    float d2 = d * d;
    float4 acc = ((const float4*)(in + (size_t)n * FEAT))[tid];
    acc.x *= d2; acc.y *= d2; acc.z *= d2; acc.w *= d2;

    int e = g_rowptr[n], e1 = g_rowptr[n + 1];
    for (; e + 4 <= e1; e += 4) {
        ull p0 = g_edge[e], p1 = g_edge[e + 1], p2 = g_edge[e + 2], p3 = g_edge[e + 3];
        int s0 = (int)(unsigned)p0, s1 = (int)(unsigned)p1;
        int s2 = (int)(unsigned)p2, s3 = (int)(unsigned)p3;
        float c0 = __uint_as_float((unsigned)(p0 >> 32));
        float c1 = __uint_as_float((unsigned)(p1 >> 32));
        float c2 = __uint_as_float((unsigned)(p2 >> 32));
        float c3 = __uint_as_float((unsigned)(p3 >> 32));
        float4 v0 = ((const float4*)(in + (size_t)s0 * FEAT))[tid];
        float4 v1 = ((const float4*)(in + (size_t)s1 * FEAT))[tid];
        float4 v2 = ((const float4*)(in + (size_t)s2 * FEAT))[tid];
        float4 v3 = ((const float4*)(in + (size_t)s3 * FEAT))[tid];
        acc.x += c0 * v0.x + c1 * v1.x + c2 * v2.x + c3 * v3.x;
        acc.y += c0 * v0.y + c1 * v1.y + c2 * v2.y + c3 * v3.y;
        acc.z += c0 * v0.z + c1 * v1.z + c2 * v2.z + c3 * v3.z;
        acc.w += c0 * v0.w + c1 * v1.w + c2 * v2.w + c3 * v3.w;
    }
    for (; e < e1; e++) {
        ull p = g_edge[e];
        int s = (int)(unsigned)p;
        float cf = __uint_as_float((unsigned)(p >> 32));
        float4 v = ((const float4*)(in + (size_t)s * FEAT))[tid];
        acc.x += cf * v.x; acc.y += cf * v.y; acc.z += cf * v.z; acc.w += cf * v.w;
    }
    ((float4*)xs)[tid] = acc;
    __syncthreads();

    int o = tid & 63, tg = tid >> 6;    // tg 0..2, 4 t's each
    float4 r = make_float4(0.f, 0.f, 0.f, 0.f);
    const float* xp = xs + tg * 4;
#pragma unroll 8
    for (int c = 0; c < 64; c++) {
        float wv = Ws[c * 65 + o];
        float4 xv = *(const float4*)(xp + c * 12);
        r.x += wv * xv.x; r.y += wv * xv.y; r.z += wv * xv.z; r.w += wv * xv.w;
    }
    float bv = bias[o];
    float4 res = make_float4(fmaxf(r.x + bv, 0.f), fmaxf(r.y + bv, 0.f),
                             fmaxf(r.z + bv, 0.f), fmaxf(r.w + bv, 0.f));
    *(float4*)(out + (size_t)n * FEAT + o * 12 + tg * 4) = res;
}

// ---------------- final conv: dot over (64,12), out (N,12) ----------------
__global__ void fin_kernel(const float* __restrict__ in, const float* __restrict__ w,
                           const float* __restrict__ b, float* __restrict__ out) {
    extern __shared__ float smf[];
    float* ws = smf;             // 12 rows, stride 772
    float* xs = smf + 12 * 772;  // 16 nodes, stride 772
    int tid = threadIdx.x;       // 192
    for (int gi = tid; gi < 12 * 192; gi += 192) {
        int o = gi / 192, j = gi - o * 192;
        ((float4*)(ws + o * 772))[j] = ((const float4*)(w + o * FEAT))[j];
    }
    int n0 = blockIdx.x * 16;
    for (int gi = tid; gi < 16 * 192; gi += 192) {
        int node = gi / 192, j = gi - node * 192;
        ((float4*)(xs + node * 772))[j] =
            ((const float4*)(in + (size_t)(n0 + node) * FEAT))[j];
    }
    __syncthreads();
    int node = tid / 12, o = tid - node * 12;
    const float* wr = ws + o * 772;
    const float* xr = xs + node * 772;
    float acc = 0.f;
#pragma unroll 4
    for (int j = 0; j < 192; j++) {
        float4 a = ((const float4*)wr)[j];
        float4 v = ((const float4*)xr)[j];
        acc += a.x * v.x + a.y * v.y + a.z * v.z + a.w * v.w;
    }
    out[(size_t)(n0 + node) * 12 + o] = acc + b[o];
}

// ---------------- launch ----------------
extern "C" void kernel_launch(void* const* d_in, const int* in_sizes, int n_in,
                              void* d_out, int out_size) {
    const float* x      = (const float*)d_in[0];
    const int*   ei     = (const int*)d_in[1];
    const float* ew     = (const float*)d_in[2];
    const float* tc1a_w = (const float*)d_in[3];
    const float* tc1a_b = (const float*)d_in[4];
    const float* gc1_w  = (const float*)d_in[5];
    const float* gc1_b  = (const float*)d_in[6];
    const float* tc1b_w = (const float*)d_in[7];
    const float* tc1b_b = (const float*)d_in[8];
    const float* tc2a_w = (const float*)d_in[9];
    const float* tc2a_b = (const float*)d_in[10];
    const float* gc2_w  = (const float*)d_in[11];
    const float* gc2_b  = (const float*)d_in[12];
    const float* tc2b_w = (const float*)d_in[13];
    const float* tc2b_b = (const float*)d_in[14];
    const float* fin_w  = (const float*)d_in[15];
    const float* fin_b  = (const float*)d_in[16];
    float* out = (float*)d_out;

    float *pA, *pB;
    ull* pW;
    cudaGetSymbolAddress((void**)&pA, g_bufA);
    cudaGetSymbolAddress((void**)&pB, g_bufB);
    cudaGetSymbolAddress((void**)&pW, g_wpk);

    const int smem32 = 3 * 32 * 64 * 8 + 4 * (32 * 12 + 8) * 4;   // 55424
    const int smem64 = 3 * 64 * 64 * 8 + 4 * (64 * 12 + 8) * 4;   // 110720
    const int smemF  = (12 + 16) * 772 * 4;                       // 86464
    cudaFuncSetAttribute(tconv_kernel<32>, cudaFuncAttributeMaxDynamicSharedMemorySize, smem32);
    cudaFuncSetAttribute(tconv_kernel<64>, cudaFuncAttributeMaxDynamicSharedMemorySize, smem64);
    cudaFuncSetAttribute(fin_kernel, cudaFuncAttributeMaxDynamicSharedMemorySize, smemF);

    // CSR build
    zero_kernel<<<(NN + 255) / 256, 256>>>();
    hist_kernel<<<(EE + 255) / 256, 256>>>(ei, ew);
    scan_kernel<<<1, 1024>>>();
    scatter_kernel<<<(EE + 255) / 256, 256>>>(ei, ew);

    // pre-pack tconv weights
    pack_w_kernel<<<(3 * 32 * 64 + 255) / 256, 256>>>(tc1a_w, pW, 32);
    pack_w_kernel<<<(3 * 64 * 64 + 255) / 256, 256>>>(tc1b_w, pW + 6144, 64);
    pack_w_kernel<<<(3 * 64 * 64 + 255) / 256, 256>>>(tc2a_w, pW + 18432, 64);
    pack_w_kernel<<<(3 * 64 * 64 + 255) / 256, 256>>>(tc2b_w, pW + 30720, 64);

    // tc1a: x -> A
    tconv_kernel<32><<<NN / 4, 256, smem32>>>(x, pW, tc1a_b, pA);
    // gcn1 (agg + W + relu): A -> B
    gcn_fused_kernel<<<NN, 192>>>(pA, pB, gc1_w, gc1_b);
    // tc1b: B -> A
    tconv_kernel<64><<<NN / 4, 256, smem64>>>(pB, pW + 6144, tc1b_b, pA);
    // tc2a: A -> B
    tconv_kernel<64><<<NN / 4, 256, smem64>>>(pA, pW + 18432, tc2a_b, pB);
    // gcn2: B -> A
    gcn_fused_kernel<<<NN, 192>>>(pB, pA, gc2_w, gc2_b);
    // tc2b: A -> B
    tconv_kernel<64><<<NN / 4, 256, smem64>>>(pA, pW + 30720, tc2b_b, pB);
    // fin: B -> out
    fin_kernel<<<NN / 16, 192, smemF>>>(pB, fin_w, fin_b, out);
}

// round 5
// speedup vs baseline: 2.8978x; 1.1904x over previous
#include <cuda_runtime.h>
#include <cuda_bf16.h>
#include <math.h>

#define NN    10000
#define EE    160000
#define FEAT  768           // 64*12
#define TOTC  120000        // NN*12 gemm columns
typedef unsigned long long ull;
typedef unsigned u32;

// ---------------- scratch (device globals; no allocation) ----------------
__device__ float g_bufA[NN * FEAT];
__device__ float g_bufB[NN * FEAT];
__device__ float g_deg[NN];
__device__ float g_dis[NN];
__device__ int   g_cnt[NN];
__device__ int   g_rowptr[NN + 1];
__device__ ull   g_edge[EE];
__device__ __nv_bfloat16 g_wbf[172032];   // prepacked hi/lo split weights, 4 layers

// ---------------- helpers ----------------
__device__ __forceinline__ u32 smem_u32(const void* p) {
    u32 a;
    asm("{ .reg .u64 t; cvta.to.shared.u64 t, %1; cvt.u32.u64 %0, t; }" : "=r"(a) : "l"(p));
    return a;
}
__device__ __forceinline__ u32 pack_bf2(float a, float b) {   // low half = a, high = b
    u32 r;
    asm("cvt.rn.satfinite.bf16x2.f32 %0, %1, %2;" : "=r"(r) : "f"(b), "f"(a));
    return r;
}
__device__ __forceinline__ void ldsm_x4(u32& r0, u32& r1, u32& r2, u32& r3, u32 a) {
    asm volatile("ldmatrix.sync.aligned.m8n8.x4.shared.b16 {%0,%1,%2,%3}, [%4];"
                 : "=r"(r0), "=r"(r1), "=r"(r2), "=r"(r3) : "r"(a));
}
__device__ __forceinline__ void ldsm_x2(u32& r0, u32& r1, u32 a) {
    asm volatile("ldmatrix.sync.aligned.m8n8.x2.shared.b16 {%0,%1}, [%2];"
                 : "=r"(r0), "=r"(r1) : "r"(a));
}
__device__ __forceinline__ void mma16816(float& d0, float& d1, float& d2, float& d3,
                                         u32 a0, u32 a1, u32 a2, u32 a3, u32 b0, u32 b1) {
    asm volatile("mma.sync.aligned.m16n8k16.row.col.f32.bf16.bf16.f32 "
                 "{%0,%1,%2,%3}, {%4,%5,%6,%7}, {%8,%9}, {%0,%1,%2,%3};"
                 : "+f"(d0), "+f"(d1), "+f"(d2), "+f"(d3)
                 : "r"(a0), "r"(a1), "r"(a2), "r"(a3), "r"(b0), "r"(b1));
}

// ---------------- CSR build ----------------
__global__ void zero_kernel() {
    int i = blockIdx.x * blockDim.x + threadIdx.x;
    if (i < NN) { g_deg[i] = 0.f; g_cnt[i] = 0; }
}
__global__ void hist_kernel(const int* __restrict__ ei, const float* __restrict__ ew) {
    int e = blockIdx.x * blockDim.x + threadIdx.x;
    if (e < EE) {
        int d = ei[EE + e];
        atomicAdd(&g_deg[d], ew[e]);
        atomicAdd(&g_cnt[d], 1);
    }
}
__global__ void scan_kernel() {
    __shared__ int sd[1024];
    int tid = threadIdx.x;
    int offset = 0;
    for (int base = 0; base < NN; base += 1024) {
        int i = base + tid;
        int v = (i < NN) ? g_cnt[i] : 0;
        if (i < NN) { g_dis[i] = rsqrtf(g_deg[i] + 1.0f); g_cnt[i] = 0; }
        sd[tid] = v;
        __syncthreads();
        for (int s = 1; s < 1024; s <<= 1) {
            int t = (tid >= s) ? sd[tid - s] : 0;
            __syncthreads();
            sd[tid] += t;
            __syncthreads();
        }
        if (i < NN) g_rowptr[i] = offset + sd[tid] - v;
        offset += sd[1023];
        __syncthreads();
    }
    if (tid == 0) g_rowptr[NN] = offset;
}
__global__ void scatter_kernel(const int* __restrict__ ei, const float* __restrict__ ew) {
    int e = blockIdx.x * blockDim.x + threadIdx.x;
    if (e < EE) {
        int d = ei[EE + e];
        int s = ei[e];
        int pos = g_rowptr[d] + atomicAdd(&g_cnt[d], 1);
        float coef = g_dis[s] * ew[e] * g_dis[d];
        g_edge[pos] = ((ull)__float_as_uint(coef) << 32) | (unsigned)s;
    }
}

// ---------------- weight prepack: hi/lo bf16 splits, P/Q-interleaved rows ----
// layout per layer: [split(2)][tap(3)][arow(128)][c(C)] bf16
// arow: within m-tile w: rows 0-7 = P gates (h = w*8+j), rows 8-15 = Q gates
__global__ void prep_w_kernel(const float* __restrict__ w0, const float* __restrict__ w1,
                              const float* __restrict__ w2, const float* __restrict__ w3) {
    int i = blockIdx.x * 256 + threadIdx.x;
    if (i >= 172032) return;
    const float* w; int C; int off;
    if (i < 24576)       { w = w0; C = 32; off = 0; }
    else if (i < 73728)  { w = w1; C = 64; off = 24576; }
    else if (i < 122880) { w = w2; C = 64; off = 73728; }
    else                 { w = w3; C = 64; off = 122880; }
    int r = i - off;
    int s = r / (384 * C);  r -= s * 384 * C;
    int tap = r / (128 * C); r -= tap * 128 * C;
    int arow = r / C;
    int c = r - arow * C;
    int j = arow & 15, wg = arow >> 4;
    int orig = (j < 8) ? (wg * 8 + j) : (64 + wg * 8 + j - 8);
    float v = w[(size_t)orig * C * 3 + c * 3 + tap];
    __nv_bfloat16 hi = __float2bfloat16(v);
    if (s == 1) hi = __float2bfloat16(v - __bfloat162float(hi));
    g_wbf[i] = hi;
}

// ---------------- input transpose: [n][32][12] -> [n][12][32] ----------------
__global__ void transpose_x_kernel(const float* __restrict__ in, float* __restrict__ out) {
    int i = blockIdx.x * 256 + threadIdx.x;
    if (i < NN * 384) {
        int c = i & 31;
        int t = (i >> 5) % 12;
        int n = i / 384;
        out[i] = in[n * 384 + c * 12 + t];
    }
}

// ---------------- tensor-core gated temporal conv (mma.sync bf16 split) -------
// xin: fp32 [n][12][C]; gw: prepacked bf16; out: fp32 [n][12][64]
template <int C>
__global__ void __launch_bounds__(256, 1)
tconv_mma_kernel(const float* __restrict__ xin, const __nv_bfloat16* __restrict__ gw,
                 const float* __restrict__ bias, float* __restrict__ out) {
    const int KS = C / 16;
    const int WST = C + 8;                 // smem row stride in bf16 units
    extern __shared__ __align__(16) __nv_bfloat16 sw[];
    const int tid = threadIdx.x;
    const int lane = tid & 31, wid = tid >> 5;
    u32 sb = smem_u32(sw);

    // ---- stage W image: 768 rows of C bf16, gmem stride C -> smem stride WST
    {
        const int U4 = C * 2 / 16;
        for (int i = tid; i < 768 * U4; i += 256) {
            int rrow = i / U4, j = i - rrow * U4;
            ((uint4*)(sw + rrow * WST))[j] = ((const uint4*)(gw + (size_t)rrow * C))[j];
        }
    }
    float bP = bias[wid * 8 + (lane >> 2)];
    float bQ = bias[64 + wid * 8 + (lane >> 2)];
    __syncthreads();

    // ---- persistent A fragments
    u32 Ah[3][KS][4], Al[3][KS][4];
#pragma unroll
    for (int tap = 0; tap < 3; tap++)
#pragma unroll
        for (int ks = 0; ks < KS; ks++) {
            int rowg = tap * 128 + wid * 16 + (lane & 15);
            u32 a = sb + (u32)((rowg * WST + ks * 16 + (lane >> 4) * 8) * 2);
            ldsm_x4(Ah[tap][ks][0], Ah[tap][ks][1], Ah[tap][ks][2], Ah[tap][ks][3], a);
            rowg += 384;
            a = sb + (u32)((rowg * WST + ks * 16 + (lane >> 4) * 8) * 2);
            ldsm_x4(Al[tap][ks][0], Al[tap][ks][1], Al[tap][ks][2], Al[tap][ks][3], a);
        }

    const int h = wid * 8 + (lane >> 2);
    const int lq = lane >> 2;         // col-within-n8 owner
    const int lc = lane & 3;

    for (int tile = blockIdx.x; tile < TOTC / 64; tile += gridDim.x) {
        int base = tile * 64;
        __syncthreads();   // previous tile's readers done

        // ---- stage X window (cols base-1 .. base+64) as bf16 hi/lo ----
        {
            const int NE4 = 66 * C / 4;
            int g0 = (base - 1) * C;
            for (int i = tid; i < NE4; i += 256) {
                int fi = i * 4;
                int s = g0 + fi;
                float4 v = make_float4(0.f, 0.f, 0.f, 0.f);
                if (s >= 0 && s + 3 < TOTC * C) v = *(const float4*)(xin + s);
                u32 hp0 = pack_bf2(v.x, v.y);
                u32 hp1 = pack_bf2(v.z, v.w);
                float r0 = v.x - __uint_as_float(hp0 << 16);
                float r1 = v.y - __uint_as_float(hp0 & 0xffff0000u);
                float r2 = v.z - __uint_as_float(hp1 << 16);
                float r3 = v.w - __uint_as_float(hp1 & 0xffff0000u);
                u32 lp0 = pack_bf2(r0, r1), lp1 = pack_bf2(r2, r3);
                int row = fi / C, c = fi - row * C;
                u32* dh = (u32*)(sw + row * WST + c);
                dh[0] = hp0; dh[1] = hp1;
                u32* dl = (u32*)(sw + (66 + row) * WST + c);
                dl[0] = lp0; dl[1] = lp1;
            }
        }
        __syncthreads();

        // ---- masks: per n-subtile, this thread's column's t ----
        int m0[8], m2[8];
#pragma unroll
        for (int ns = 0; ns < 8; ns++) {
            int tm = (base + ns * 8 + lq) % 12;
            m0[ns] = (tm == 0);
            m2[ns] = (tm == 11);
        }

        float d[8][4];
#pragma unroll
        for (int ns = 0; ns < 8; ns++) { d[ns][0] = d[ns][1] = d[ns][2] = d[ns][3] = 0.f; }

#pragma unroll
        for (int ks = 0; ks < KS; ks++)
#pragma unroll
            for (int tap = 0; tap < 3; tap++)
#pragma unroll
                for (int ns = 0; ns < 8; ns++) {
                    int xrow = ns * 8 + tap + (lane & 7);
                    int kk = ks * 16 + ((lane >> 3) & 1) * 8;
                    u32 ah = sb + (u32)((xrow * WST + kk) * 2);
                    u32 bh0, bh1, bl0, bl1;
                    ldsm_x2(bh0, bh1, ah);
                    ldsm_x2(bl0, bl1, ah + (u32)(66 * WST * 2));
                    if (tap == 0 && m0[ns]) { bh0 = bh1 = bl0 = bl1 = 0u; }
                    if (tap == 2 && m2[ns]) { bh0 = bh1 = bl0 = bl1 = 0u; }
                    mma16816(d[ns][0], d[ns][1], d[ns][2], d[ns][3],
                             Ah[tap][ks][0], Ah[tap][ks][1], Ah[tap][ks][2], Ah[tap][ks][3],
                             bh0, bh1);
                    mma16816(d[ns][0], d[ns][1], d[ns][2], d[ns][3],
                             Ah[tap][ks][0], Ah[tap][ks][1], Ah[tap][ks][2], Ah[tap][ks][3],
                             bl0, bl1);
                    mma16816(d[ns][0], d[ns][1], d[ns][2], d[ns][3],
                             Al[tap][ks][0], Al[tap][ks][1], Al[tap][ks][2], Al[tap][ks][3],
                             bh0, bh1);
                }

        // ---- epilogue: gate in-register (c0,c1)=P, (c2,c3)=Q of same h ----
#pragma unroll
        for (int ns = 0; ns < 8; ns++) {
            int col0 = base + ns * 8 + 2 * lc;
            float s2 = 1.f / (1.f + __expf(-(d[ns][2] + bQ)));
            float s3 = 1.f / (1.f + __expf(-(d[ns][3] + bQ)));
            out[(size_t)col0 * 64 + h]       = (d[ns][0] + bP) * s2;
            out[(size_t)(col0 + 1) * 64 + h] = (d[ns][1] + bP) * s3;
        }
    }
}

// ---------------- fused GCN (layout [n][t][c]) ----------------
__global__ void __launch_bounds__(192)
gcn_fused_kernel(const float* __restrict__ in, float* __restrict__ out,
                 const float* __restrict__ W, const float* __restrict__ bias) {
    __shared__ __align__(16) float xs[768];
    __shared__ float Ws[64 * 65];
    int n = blockIdx.x, tid = threadIdx.x;

    for (int gi = tid; gi < 4096; gi += 192) {
        int o = gi >> 6, c = gi & 63;
        Ws[c * 65 + o] = W[gi];
    }

    float d = g_dis[n];
    float d2 = d * d;
    float4 acc = ((const float4*)(in + (size_t)n * FEAT))[tid];
    acc.x *= d2; acc.y *= d2; acc.z *= d2; acc.w *= d2;

    int e = g_rowptr[n], e1 = g_rowptr[n + 1];
    for (; e + 4 <= e1; e += 4) {
        ull p0 = g_edge[e], p1 = g_edge[e + 1], p2 = g_edge[e + 2], p3 = g_edge[e + 3];
        int s0 = (int)(unsigned)p0, s1 = (int)(unsigned)p1;
        int s2 = (int)(unsigned)p2, s3 = (int)(unsigned)p3;
        float c0 = __uint_as_float((unsigned)(p0 >> 32));
        float c1 = __uint_as_float((unsigned)(p1 >> 32));
        float c2 = __uint_as_float((unsigned)(p2 >> 32));
        float c3 = __uint_as_float((unsigned)(p3 >> 32));
        float4 v0 = ((const float4*)(in + (size_t)s0 * FEAT))[tid];
        float4 v1 = ((const float4*)(in + (size_t)s1 * FEAT))[tid];
        float4 v2 = ((const float4*)(in + (size_t)s2 * FEAT))[tid];
        float4 v3 = ((const float4*)(in + (size_t)s3 * FEAT))[tid];
        acc.x += c0 * v0.x + c1 * v1.x + c2 * v2.x + c3 * v3.x;
        acc.y += c0 * v0.y + c1 * v1.y + c2 * v2.y + c3 * v3.y;
        acc.z += c0 * v0.z + c1 * v1.z + c2 * v2.z + c3 * v3.z;
        acc.w += c0 * v0.w + c1 * v1.w + c2 * v2.w + c3 * v3.w;
    }
    for (; e < e1; e++) {
        ull p = g_edge[e];
        int s = (int)(unsigned)p;
        float cf = __uint_as_float((unsigned)(p >> 32));
        float4 v = ((const float4*)(in + (size_t)s * FEAT))[tid];
        acc.x += cf * v.x; acc.y += cf * v.y; acc.z += cf * v.z; acc.w += cf * v.w;
    }
    ((float4*)xs)[tid] = acc;
    __syncthreads();

    // out[t][o] = relu(sum_c W[o][c] * xs[t*64+c] + b[o])
    int o = tid & 63, tg = tid >> 6;
    float a0 = 0.f, a1 = 0.f, a2 = 0.f, a3 = 0.f;
#pragma unroll 8
    for (int c = 0; c < 64; c++) {
        float wv = Ws[c * 65 + o];
        const float* xp = xs + c;
        a0 += wv * xp[(tg * 4 + 0) * 64];
        a1 += wv * xp[(tg * 4 + 1) * 64];
        a2 += wv * xp[(tg * 4 + 2) * 64];
        a3 += wv * xp[(tg * 4 + 3) * 64];
    }
    float bv = bias[o];
    float* ob = out + (size_t)n * FEAT + o;
    ob[(tg * 4 + 0) * 64] = fmaxf(a0 + bv, 0.f);
    ob[(tg * 4 + 1) * 64] = fmaxf(a1 + bv, 0.f);
    ob[(tg * 4 + 2) * 64] = fmaxf(a2 + bv, 0.f);
    ob[(tg * 4 + 3) * 64] = fmaxf(a3 + bv, 0.f);
}

// ---------------- final conv (layout [n][t][c]) ----------------
__global__ void fin_kernel(const float* __restrict__ in, const float* __restrict__ w,
                           const float* __restrict__ b, float* __restrict__ out) {
    extern __shared__ float smf[];
    float* wt = smf;              // 12 rows, stride 772, reindexed [t*64+h]
    float* xt = smf + 12 * 772;   // 16 nodes, stride 772
    int tid = threadIdx.x;        // 192
    for (int i = tid; i < 12 * 768; i += 192) {
        int o = i / 768, r = i - o * 768;
        int t = r >> 6, hh = r & 63;
        wt[o * 772 + r] = w[o * 768 + hh * 12 + t];
    }
    int n0 = blockIdx.x * 16;
    for (int gi = tid; gi < 16 * 192; gi += 192) {
        int node = gi / 192, j = gi - node * 192;
        ((float4*)(xt + node * 772))[j] =
            ((const float4*)(in + (size_t)(n0 + node) * FEAT))[j];
    }
    __syncthreads();
    int node = tid / 12, o = tid - node * 12;
    const float* wr = wt + o * 772;
    const float* xr = xt + node * 772;
    float acc = 0.f;
#pragma unroll 4
    for (int j = 0; j < 192; j++) {
        float4 a = ((const float4*)wr)[j];
        float4 v = ((const float4*)xr)[j];
        acc += a.x * v.x + a.y * v.y + a.z * v.z + a.w * v.w;
    }
    out[(size_t)(n0 + node) * 12 + o] = acc + b[o];
}

// ---------------- launch ----------------
extern "C" void kernel_launch(void* const* d_in, const int* in_sizes, int n_in,
                              void* d_out, int out_size) {
    const float* x      = (const float*)d_in[0];
    const int*   ei     = (const int*)d_in[1];
    const float* ew     = (const float*)d_in[2];
    const float* tc1a_w = (const float*)d_in[3];
    const float* tc1a_b = (const float*)d_in[4];
    const float* gc1_w  = (const float*)d_in[5];
    const float* gc1_b  = (const float*)d_in[6];
    const float* tc1b_w = (const float*)d_in[7];
    const float* tc1b_b = (const float*)d_in[8];
    const float* tc2a_w = (const float*)d_in[9];
    const float* tc2a_b = (const float*)d_in[10];
    const float* gc2_w  = (const float*)d_in[11];
    const float* gc2_b  = (const float*)d_in[12];
    const float* tc2b_w = (const float*)d_in[13];
    const float* tc2b_b = (const float*)d_in[14];
    const float* fin_w  = (const float*)d_in[15];
    const float* fin_b  = (const float*)d_in[16];
    float* out = (float*)d_out;

    float* pA; float* pB; __nv_bfloat16* pW;
    cudaGetSymbolAddress((void**)&pA, g_bufA);
    cudaGetSymbolAddress((void**)&pB, g_bufB);
    cudaGetSymbolAddress((void**)&pW, g_wbf);

    const int smem32 = 768 * 40 * 2;    // 61440
    const int smem64 = 768 * 72 * 2;    // 110592
    const int smemF  = (12 + 16) * 772 * 4;
    cudaFuncSetAttribute(tconv_mma_kernel<32>, cudaFuncAttributeMaxDynamicSharedMemorySize, smem32);
    cudaFuncSetAttribute(tconv_mma_kernel<64>, cudaFuncAttributeMaxDynamicSharedMemorySize, smem64);
    cudaFuncSetAttribute(fin_kernel, cudaFuncAttributeMaxDynamicSharedMemorySize, smemF);

    // order chosen so the big mma kernel lands in the ncu capture slot (#4)
    zero_kernel<<<(NN + 255) / 256, 256>>>();
    prep_w_kernel<<<(172032 + 255) / 256, 256>>>(tc1a_w, tc1b_w, tc2a_w, tc2b_w);
    transpose_x_kernel<<<(NN * 384 + 255) / 256, 256>>>(x, pA);
    // tc1a: A -> B
    tconv_mma_kernel<32><<<296, 256, smem32>>>(pA, pW, tc1a_b, pB);
    hist_kernel<<<(EE + 255) / 256, 256>>>(ei, ew);
    scan_kernel<<<1, 1024>>>();
    scatter_kernel<<<(EE + 255) / 256, 256>>>(ei, ew);
    // gcn1: B -> A
    gcn_fused_kernel<<<NN, 192>>>(pB, pA, gc1_w, gc1_b);
    // tc1b: A -> B
    tconv_mma_kernel<64><<<148, 256, smem64>>>(pA, pW + 24576, tc1b_b, pB);
    // tc2a: B -> A
    tconv_mma_kernel<64><<<148, 256, smem64>>>(pB, pW + 73728, tc2a_b, pA);
    // gcn2: A -> B
    gcn_fused_kernel<<<NN, 192>>>(pA, pB, gc2_w, gc2_b);
    // tc2b: B -> A
    tconv_mma_kernel<64><<<148, 256, smem64>>>(pB, pW + 122880, tc2b_b, pA);
    // fin: A -> out
    fin_kernel<<<NN / 16, 192, smemF>>>(pA, fin_w, fin_b, out);
}

// round 7
// speedup vs baseline: 3.3724x; 1.1638x over previous
#include <cuda_runtime.h>
#include <cuda_bf16.h>
#include <math.h>

#define NN    10000
#define EE    160000
#define FEAT  768           // 64*12
#define TOTC  120000        // NN*12 gemm columns
typedef unsigned long long ull;
typedef unsigned u32;

// ---------------- scratch (device globals; no allocation) ----------------
__device__ float g_bufA[NN * FEAT];
__device__ float g_bufB[NN * FEAT];
__device__ float g_deg[NN];
__device__ float g_dis[NN];
__device__ int   g_cnt[NN];
__device__ int   g_rowptr[NN + 1];
__device__ ull   g_edge[EE];
__device__ u32   g_wfrag[86016];   // frag-ordered hi/lo weights, 4 layers (uint4 units/4)

// ---------------- helpers ----------------
__device__ __forceinline__ u32 smem_u32(const void* p) {
    u32 a;
    asm("{ .reg .u64 t; cvta.to.shared.u64 t, %1; cvt.u32.u64 %0, t; }" : "=r"(a) : "l"(p));
    return a;
}
__device__ __forceinline__ u32 pack_bf2(float a, float b) {   // low half = a, high = b
    u32 r;
    asm("cvt.rn.satfinite.bf16x2.f32 %0, %1, %2;" : "=r"(r) : "f"(b), "f"(a));
    return r;
}
__device__ __forceinline__ void ldsm_x4(u32& r0, u32& r1, u32& r2, u32& r3, u32 a) {
    asm volatile("ldmatrix.sync.aligned.m8n8.x4.shared.b16 {%0,%1,%2,%3}, [%4];"
                 : "=r"(r0), "=r"(r1), "=r"(r2), "=r"(r3) : "r"(a));
}
__device__ __forceinline__ void mma16816(float& d0, float& d1, float& d2, float& d3,
                                         u32 a0, u32 a1, u32 a2, u32 a3, u32 b0, u32 b1) {
    asm volatile("mma.sync.aligned.m16n8k16.row.col.f32.bf16.bf16.f32 "
                 "{%0,%1,%2,%3}, {%4,%5,%6,%7}, {%8,%9}, {%0,%1,%2,%3};"
                 : "+f"(d0), "+f"(d1), "+f"(d2), "+f"(d3)
                 : "r"(a0), "r"(a1), "r"(a2), "r"(a3), "r"(b0), "r"(b1));
}

// ---------------- CSR build ----------------
__global__ void zero_kernel() {
    int i = blockIdx.x * blockDim.x + threadIdx.x;
    if (i < NN) { g_deg[i] = 0.f; g_cnt[i] = 0; }
}
__global__ void hist_kernel(const int* __restrict__ ei, const float* __restrict__ ew) {
    int e = blockIdx.x * blockDim.x + threadIdx.x;
    if (e < EE) {
        int d = ei[EE + e];
        atomicAdd(&g_deg[d], ew[e]);
        atomicAdd(&g_cnt[d], 1);
    }
}
__global__ void scan_kernel() {
    __shared__ int sd[1024];
    int tid = threadIdx.x;
    int offset = 0;
    for (int base = 0; base < NN; base += 1024) {
        int i = base + tid;
        int v = (i < NN) ? g_cnt[i] : 0;
        if (i < NN) { g_dis[i] = rsqrtf(g_deg[i] + 1.0f); g_cnt[i] = 0; }
        sd[tid] = v;
        __syncthreads();
        for (int s = 1; s < 1024; s <<= 1) {
            int t = (tid >= s) ? sd[tid - s] : 0;
            __syncthreads();
            sd[tid] += t;
            __syncthreads();
        }
        if (i < NN) g_rowptr[i] = offset + sd[tid] - v;
        offset += sd[1023];
        __syncthreads();
    }
    if (tid == 0) g_rowptr[NN] = offset;
}
__global__ void scatter_kernel(const int* __restrict__ ei, const float* __restrict__ ew) {
    int e = blockIdx.x * blockDim.x + threadIdx.x;
    if (e < EE) {
        int d = ei[EE + e];
        int s = ei[e];
        int pos = g_rowptr[d] + atomicAdd(&g_cnt[d], 1);
        float coef = g_dis[s] * ew[e] * g_dis[d];
        g_edge[pos] = ((ull)__float_as_uint(coef) << 32) | (unsigned)s;
    }
}

// ---------------- weight prepack -> mma fragment order ----------------
// uint4 index v -> (s, tap, ks, wid, lane); each uint4 = a-regs r0..r3 (2 bf16 each)
__global__ void prep_w_kernel(const float* __restrict__ w0, const float* __restrict__ w1,
                              const float* __restrict__ w2, const float* __restrict__ w3) {
    int v = blockIdx.x * 256 + threadIdx.x;
    if (v >= 21504) return;
    const float* w; int C, off;
    if (v < 3072)       { w = w0; C = 32; off = 0; }
    else if (v < 9216)  { w = w1; C = 64; off = 3072; }
    else if (v < 15360) { w = w2; C = 64; off = 9216; }
    else                { w = w3; C = 64; off = 15360; }
    int r = v - off;
    int KS = C / 16;
    int lane = r & 31; r >>= 5;
    int wid = r & 7;  r >>= 3;
    int ks = r % KS;  r /= KS;
    int tap = r % 3;  r /= 3;
    int s = r;
    u32 o4[4];
#pragma unroll
    for (int rr = 0; rr < 4; rr++) {
        float vv[2];
#pragma unroll
        for (int b = 0; b < 2; b++) {
            int m_local = (rr & 1) * 8 + (lane >> 2);
            int k = (rr >> 1) * 8 + (lane & 3) * 2 + b;
            int hh = wid * 8 + (m_local & 7);
            int orig = (m_local < 8) ? hh : 64 + hh;
            int c = ks * 16 + k;
            float val = w[(size_t)orig * C * 3 + c * 3 + tap];
            float hi = __bfloat162float(__float2bfloat16(val));
            vv[b] = (s == 0) ? hi : (val - hi);
        }
        o4[rr] = pack_bf2(vv[0], vv[1]);
    }
    ((uint4*)g_wfrag)[v] = make_uint4(o4[0], o4[1], o4[2], o4[3]);
}

// ---------------- input transpose: [n][32][12] -> [n][12][32] ----------------
__global__ void transpose_x_kernel(const float* __restrict__ in, float* __restrict__ out) {
    int i = blockIdx.x * 256 + threadIdx.x;
    if (i < NN * 384) {
        int c = i & 31;
        int t = (i >> 5) % 12;
        int n = i / 384;
        out[i] = in[n * 384 + c * 12 + t];
    }
}

// ---------------- tensor-core gated temporal conv (mma.sync bf16 split) -------
// xin: fp32 [n][12][C]; wf: frag-ordered bf16 (uint4); out: fp32 [n][12][64]
template <int C>
__global__ void __launch_bounds__(256, 2)
tconv_mma_kernel(const float* __restrict__ xin, const uint4* __restrict__ wf,
                 const float* __restrict__ bias, float* __restrict__ out) {
    const int KS = C / 16;
    const int PAIRS = KS / 2;
    const int WST = C + 8;                 // smem row stride in bf16 units
    extern __shared__ __align__(16) __nv_bfloat16 sw[];  // 132 rows x WST (hi 0-65, lo 66-131)
    const int tid = threadIdx.x;
    const int lane = tid & 31, wid = tid >> 5;
    u32 sb = smem_u32(sw);

    float bP = bias[wid * 8 + (lane >> 2)];
    float bQ = bias[64 + wid * 8 + (lane >> 2)];
    const int h = wid * 8 + (lane >> 2);
    const int lq = lane >> 2;
    const int lc = lane & 3;

    for (int tile = blockIdx.x; tile < TOTC / 64; tile += gridDim.x) {
        int base = tile * 64;
        __syncthreads();   // previous tile's readers done

        // ---- stage X window (cols base-1 .. base+64) as bf16 hi/lo ----
        {
            const int NE4 = 66 * C / 4;
            int g0 = (base - 1) * C;
            for (int i = tid; i < NE4; i += 256) {
                int fi = i * 4;
                int s = g0 + fi;
                float4 v = make_float4(0.f, 0.f, 0.f, 0.f);
                if (s >= 0 && s + 3 < TOTC * C) v = *(const float4*)(xin + s);
                u32 hp0 = pack_bf2(v.x, v.y);
                u32 hp1 = pack_bf2(v.z, v.w);
                float r0 = v.x - __uint_as_float(hp0 << 16);
                float r1 = v.y - __uint_as_float(hp0 & 0xffff0000u);
                float r2 = v.z - __uint_as_float(hp1 << 16);
                float r3 = v.w - __uint_as_float(hp1 & 0xffff0000u);
                u32 lp0 = pack_bf2(r0, r1), lp1 = pack_bf2(r2, r3);
                int row = fi / C, c = fi - row * C;
                u32* dh = (u32*)(sw + row * WST + c);
                dh[0] = hp0; dh[1] = hp1;
                u32* dl = (u32*)(sw + (66 + row) * WST + c);
                dl[0] = lp0; dl[1] = lp1;
            }
        }
        __syncthreads();

        // ---- per-column boundary masks ----
        int m0[8], m2[8];
#pragma unroll
        for (int ns = 0; ns < 8; ns++) {
            int tm = (base + ns * 8 + lq) % 12;
            m0[ns] = (tm == 0);
            m2[ns] = (tm == 11);
        }

        float d[8][4];
#pragma unroll
        for (int ns = 0; ns < 8; ns++) { d[ns][0] = d[ns][1] = d[ns][2] = d[ns][3] = 0.f; }

#pragma unroll
        for (int pair = 0; pair < PAIRS; pair++) {
            // A fragments for this k-pair: LDG.128 (L1-resident), 12 per warp
            uint4 AH[3][2], AL[3][2];
#pragma unroll
            for (int tap = 0; tap < 3; tap++)
#pragma unroll
                for (int k2 = 0; k2 < 2; k2++) {
                    AH[tap][k2] = wf[((tap * KS + pair * 2 + k2) * 8 + wid) * 32 + lane];
                    AL[tap][k2] = wf[(((3 + tap) * KS + pair * 2 + k2) * 8 + wid) * 32 + lane];
                }
#pragma unroll
            for (int ns = 0; ns < 8; ns++) {
#pragma unroll
                for (int tap = 0; tap < 3; tap++) {
                    int row = ns * 8 + tap + (lane & 7);
                    int kk = pair * 32 + ((lane >> 3) & 3) * 8;
                    u32 a = sb + (u32)((row * WST + kk) * 2);
                    u32 b0, b1, b2, b3, l0, l1, l2, l3;
                    ldsm_x4(b0, b1, b2, b3, a);
                    ldsm_x4(l0, l1, l2, l3, a + (u32)(66 * WST * 2));
                    if (tap == 0 && m0[ns]) { b0 = b1 = b2 = b3 = l0 = l1 = l2 = l3 = 0u; }
                    if (tap == 2 && m2[ns]) { b0 = b1 = b2 = b3 = l0 = l1 = l2 = l3 = 0u; }
                    // ks even of pair
                    mma16816(d[ns][0], d[ns][1], d[ns][2], d[ns][3],
                             AH[tap][0].x, AH[tap][0].y, AH[tap][0].z, AH[tap][0].w, b0, b1);
                    mma16816(d[ns][0], d[ns][1], d[ns][2], d[ns][3],
                             AH[tap][0].x, AH[tap][0].y, AH[tap][0].z, AH[tap][0].w, l0, l1);
                    mma16816(d[ns][0], d[ns][1], d[ns][2], d[ns][3],
                             AL[tap][0].x, AL[tap][0].y, AL[tap][0].z, AL[tap][0].w, b0, b1);
                    // ks odd of pair
                    mma16816(d[ns][0], d[ns][1], d[ns][2], d[ns][3],
                             AH[tap][1].x, AH[tap][1].y, AH[tap][1].z, AH[tap][1].w, b2, b3);
                    mma16816(d[ns][0], d[ns][1], d[ns][2], d[ns][3],
                             AH[tap][1].x, AH[tap][1].y, AH[tap][1].z, AH[tap][1].w, l2, l3);
                    mma16816(d[ns][0], d[ns][1], d[ns][2], d[ns][3],
                             AL[tap][1].x, AL[tap][1].y, AL[tap][1].z, AL[tap][1].w, b2, b3);
                }
            }
        }

        // ---- epilogue: gate in-register (c0,c1)=P, (c2,c3)=Q of same h ----
#pragma unroll
        for (int ns = 0; ns < 8; ns++) {
            int col0 = base + ns * 8 + 2 * lc;
            float s2 = 1.f / (1.f + __expf(-(d[ns][2] + bQ)));
            float s3 = 1.f / (1.f + __expf(-(d[ns][3] + bQ)));
            out[(size_t)col0 * 64 + h]       = (d[ns][0] + bP) * s2;
            out[(size_t)(col0 + 1) * 64 + h] = (d[ns][1] + bP) * s3;
        }
    }
}

// ---------------- fused GCN (layout [n][t][c]) ----------------
__global__ void __launch_bounds__(192)
gcn_fused_kernel(const float* __restrict__ in, float* __restrict__ out,
                 const float* __restrict__ W, const float* __restrict__ bias) {
    __shared__ __align__(16) float xs[768];
    __shared__ float Ws[64 * 65];
    int n = blockIdx.x, tid = threadIdx.x;

    for (int gi = tid; gi < 4096; gi += 192) {
        int o = gi >> 6, c = gi & 63;
        Ws[c * 65 + o] = W[gi];
    }

    float d = g_dis[n];
    float d2 = d * d;
    float4 acc = ((const float4*)(in + (size_t)n * FEAT))[tid];
    acc.x *= d2; acc.y *= d2; acc.z *= d2; acc.w *= d2;

    int e = g_rowptr[n], e1 = g_rowptr[n + 1];
    for (; e + 4 <= e1; e += 4) {
        ull p0 = g_edge[e], p1 = g_edge[e + 1], p2 = g_edge[e + 2], p3 = g_edge[e + 3];
        int s0 = (int)(unsigned)p0, s1 = (int)(unsigned)p1;
        int s2 = (int)(unsigned)p2, s3 = (int)(unsigned)p3;
        float c0 = __uint_as_float((unsigned)(p0 >> 32));
        float c1 = __uint_as_float((unsigned)(p1 >> 32));
        float c2 = __uint_as_float((unsigned)(p2 >> 32));
        float c3 = __uint_as_float((unsigned)(p3 >> 32));
        float4 v0 = ((const float4*)(in + (size_t)s0 * FEAT))[tid];
        float4 v1 = ((const float4*)(in + (size_t)s1 * FEAT))[tid];
        float4 v2 = ((const float4*)(in + (size_t)s2 * FEAT))[tid];
        float4 v3 = ((const float4*)(in + (size_t)s3 * FEAT))[tid];
        acc.x += c0 * v0.x + c1 * v1.x + c2 * v2.x + c3 * v3.x;
        acc.y += c0 * v0.y + c1 * v1.y + c2 * v2.y + c3 * v3.y;
        acc.z += c0 * v0.z + c1 * v1.z + c2 * v2.z + c3 * v3.z;
        acc.w += c0 * v0.w + c1 * v1.w + c2 * v2.w + c3 * v3.w;
    }
    for (; e < e1; e++) {
        ull p = g_edge[e];
        int s = (int)(unsigned)p;
        float cf = __uint_as_float((unsigned)(p >> 32));
        float4 v = ((const float4*)(in + (size_t)s * FEAT))[tid];
        acc.x += cf * v.x; acc.y += cf * v.y; acc.z += cf * v.z; acc.w += cf * v.w;
    }
    ((float4*)xs)[tid] = acc;
    __syncthreads();

    int o = tid & 63, tg = tid >> 6;
    float a0 = 0.f, a1 = 0.f, a2 = 0.f, a3 = 0.f;
#pragma unroll 8
    for (int c = 0; c < 64; c++) {
        float wv = Ws[c * 65 + o];
        const float* xp = xs + c;
        a0 += wv * xp[(tg * 4 + 0) * 64];
        a1 += wv * xp[(tg * 4 + 1) * 64];
        a2 += wv * xp[(tg * 4 + 2) * 64];
        a3 += wv * xp[(tg * 4 + 3) * 64];
    }
    float bv = bias[o];
    float* ob = out + (size_t)n * FEAT + o;
    ob[(tg * 4 + 0) * 64] = fmaxf(a0 + bv, 0.f);
    ob[(tg * 4 + 1) * 64] = fmaxf(a1 + bv, 0.f);
    ob[(tg * 4 + 2) * 64] = fmaxf(a2 + bv, 0.f);
    ob[(tg * 4 + 3) * 64] = fmaxf(a3 + bv, 0.f);
}

// ---------------- final conv (layout [n][t][c]) ----------------
__global__ void fin_kernel(const float* __restrict__ in, const float* __restrict__ w,
                           const float* __restrict__ b, float* __restrict__ out) {
    extern __shared__ float smf[];
    float* wt = smf;              // 12 rows, stride 772, reindexed [t*64+h]
    float* xt = smf + 12 * 772;   // 16 nodes, stride 772
    int tid = threadIdx.x;        // 192
    for (int i = tid; i < 12 * 768; i += 192) {
        int o = i / 768, r = i - o * 768;
        int t = r >> 6, hh = r & 63;
        wt[o * 772 + r] = w[o * 768 + hh * 12 + t];
    }
    int n0 = blockIdx.x * 16;
    for (int gi = tid; gi < 16 * 192; gi += 192) {
        int node = gi / 192, j = gi - node * 192;
        ((float4*)(xt + node * 772))[j] =
            ((const float4*)(in + (size_t)(n0 + node) * FEAT))[j];
    }
    __syncthreads();
    int node = tid / 12, o = tid - node * 12;
    const float* wr = wt + o * 772;
    const float* xr = xt + node * 772;
    float acc = 0.f;
#pragma unroll 4
    for (int j = 0; j < 192; j++) {
        float4 a = ((const float4*)wr)[j];
        float4 v = ((const float4*)xr)[j];
        acc += a.x * v.x + a.y * v.y + a.z * v.z + a.w * v.w;
    }
    out[(size_t)(n0 + node) * 12 + o] = acc + b[o];
}

// ---------------- launch ----------------
extern "C" void kernel_launch(void* const* d_in, const int* in_sizes, int n_in,
                              void* d_out, int out_size) {
    const float* x      = (const float*)d_in[0];
    const int*   ei     = (const int*)d_in[1];
    const float* ew     = (const float*)d_in[2];
    const float* tc1a_w = (const float*)d_in[3];
    const float* tc1a_b = (const float*)d_in[4];
    const float* gc1_w  = (const float*)d_in[5];
    const float* gc1_b  = (const float*)d_in[6];
    const float* tc1b_w = (const float*)d_in[7];
    const float* tc1b_b = (const float*)d_in[8];
    const float* tc2a_w = (const float*)d_in[9];
    const float* tc2a_b = (const float*)d_in[10];
    const float* gc2_w  = (const float*)d_in[11];
    const float* gc2_b  = (const float*)d_in[12];
    const float* tc2b_w = (const float*)d_in[13];
    const float* tc2b_b = (const float*)d_in[14];
    const float* fin_w  = (const float*)d_in[15];
    const float* fin_b  = (const float*)d_in[16];
    float* out = (float*)d_out;

    float* pA; float* pB; uint4* pW;
    cudaGetSymbolAddress((void**)&pA, g_bufA);
    cudaGetSymbolAddress((void**)&pB, g_bufB);
    cudaGetSymbolAddress((void**)&pW, g_wfrag);

    const int smem32 = 132 * 40 * 2;    // 10560
    const int smem64 = 132 * 72 * 2;    // 19008
    const int smemF  = (12 + 16) * 772 * 4;
    cudaFuncSetAttribute(fin_kernel, cudaFuncAttributeMaxDynamicSharedMemorySize, smemF);

    // order: big mma kernel in the ncu capture slot (#4)
    zero_kernel<<<(NN + 255) / 256, 256>>>();
    prep_w_kernel<<<(21504 + 255) / 256, 256>>>(tc1a_w, tc1b_w, tc2a_w, tc2b_w);
    transpose_x_kernel<<<(NN * 384 + 255) / 256, 256>>>(x, pA);
    // tc1a: A -> B
    tconv_mma_kernel<32><<<296, 256, smem32>>>(pA, pW, tc1a_b, pB);
    hist_kernel<<<(EE + 255) / 256, 256>>>(ei, ew);
    scan_kernel<<<1, 1024>>>();
    scatter_kernel<<<(EE + 255) / 256, 256>>>(ei, ew);
    // gcn1: B -> A
    gcn_fused_kernel<<<NN, 192>>>(pB, pA, gc1_w, gc1_b);
    // tc1b: A -> B
    tconv_mma_kernel<64><<<296, 256, smem64>>>(pA, pW + 3072, tc1b_b, pB);
    // tc2a: B -> A
    tconv_mma_kernel<64><<<296, 256, smem64>>>(pB, pW + 9216, tc2a_b, pA);
    // gcn2: A -> B
    gcn_fused_kernel<<<NN, 192>>>(pA, pB, gc2_w, gc2_b);
    // tc2b: B -> A
    tconv_mma_kernel<64><<<296, 256, smem64>>>(pB, pW + 15360, tc2b_b, pA);
    // fin: A -> out
    fin_kernel<<<NN / 16, 192, smemF>>>(pA, fin_w, fin_b, out);
}

// round 8
// speedup vs baseline: 3.4356x; 1.0187x over previous
#include <cuda_runtime.h>
#include <cuda_bf16.h>
#include <math.h>

#define NN    10000
#define EE    160000
#define FEAT  768           // 64*12
#define TOTC  120000        // NN*12 gemm columns
typedef unsigned long long ull;
typedef unsigned u32;

// ---------------- scratch (device globals; no allocation) ----------------
__device__ float g_bufA[NN * FEAT];
__device__ float g_bufB[NN * FEAT];
__device__ __nv_bfloat16 g_h1[NN * FEAT];
__device__ __nv_bfloat16 g_l1[NN * FEAT];
__device__ __nv_bfloat16 g_h2[NN * FEAT];
__device__ __nv_bfloat16 g_l2[NN * FEAT];
__device__ float g_deg[NN];
__device__ float g_dis[NN];
__device__ int   g_cnt[NN];
__device__ int   g_rowptr[NN + 1];
__device__ ull   g_edge[EE];
__device__ u32   g_wfrag[86016];   // frag-ordered hi/lo weights, 4 layers

// ---------------- helpers ----------------
__device__ __forceinline__ u32 smem_u32(const void* p) {
    u32 a;
    asm("{ .reg .u64 t; cvta.to.shared.u64 t, %1; cvt.u32.u64 %0, t; }" : "=r"(a) : "l"(p));
    return a;
}
__device__ __forceinline__ u32 pack_bf2(float a, float b) {   // low half = a, high = b
    u32 r;
    asm("cvt.rn.satfinite.bf16x2.f32 %0, %1, %2;" : "=r"(r) : "f"(b), "f"(a));
    return r;
}
__device__ __forceinline__ void ldsm_x4(u32& r0, u32& r1, u32& r2, u32& r3, u32 a) {
    asm volatile("ldmatrix.sync.aligned.m8n8.x4.shared.b16 {%0,%1,%2,%3}, [%4];"
                 : "=r"(r0), "=r"(r1), "=r"(r2), "=r"(r3) : "r"(a));
}
__device__ __forceinline__ void mma16816(float& d0, float& d1, float& d2, float& d3,
                                         u32 a0, u32 a1, u32 a2, u32 a3, u32 b0, u32 b1) {
    asm volatile("mma.sync.aligned.m16n8k16.row.col.f32.bf16.bf16.f32 "
                 "{%0,%1,%2,%3}, {%4,%5,%6,%7}, {%8,%9}, {%0,%1,%2,%3};"
                 : "+f"(d0), "+f"(d1), "+f"(d2), "+f"(d3)
                 : "r"(a0), "r"(a1), "r"(a2), "r"(a3), "r"(b0), "r"(b1));
}
__device__ __forceinline__ void cp_async16(u32 dst, const void* src, bool v) {
    asm volatile("cp.async.cg.shared.global [%0], [%1], 16, %2;"
                 :: "r"(dst), "l"(src), "r"(v ? 16 : 0));
}
#define CP_COMMIT() asm volatile("cp.async.commit_group;" ::: "memory")
#define CP_WAIT1()  asm volatile("cp.async.wait_group 1;" ::: "memory")
#define CP_WAIT0()  asm volatile("cp.async.wait_group 0;" ::: "memory")

// ---------------- CSR build ----------------
__global__ void zero_kernel() {
    int i = blockIdx.x * blockDim.x + threadIdx.x;
    if (i < NN) { g_deg[i] = 0.f; g_cnt[i] = 0; }
}
__global__ void hist_kernel(const int* __restrict__ ei, const float* __restrict__ ew) {
    int e = blockIdx.x * blockDim.x + threadIdx.x;
    if (e < EE) {
        int d = ei[EE + e];
        atomicAdd(&g_deg[d], ew[e]);
        atomicAdd(&g_cnt[d], 1);
    }
}
__global__ void scan_kernel() {
    __shared__ int sd[1024];
    int tid = threadIdx.x;
    int offset = 0;
    for (int base = 0; base < NN; base += 1024) {
        int i = base + tid;
        int v = (i < NN) ? g_cnt[i] : 0;
        if (i < NN) { g_dis[i] = rsqrtf(g_deg[i] + 1.0f); g_cnt[i] = 0; }
        sd[tid] = v;
        __syncthreads();
        for (int s = 1; s < 1024; s <<= 1) {
            int t = (tid >= s) ? sd[tid - s] : 0;
            __syncthreads();
            sd[tid] += t;
            __syncthreads();
        }
        if (i < NN) g_rowptr[i] = offset + sd[tid] - v;
        offset += sd[1023];
        __syncthreads();
    }
    if (tid == 0) g_rowptr[NN] = offset;
}
__global__ void scatter_kernel(const int* __restrict__ ei, const float* __restrict__ ew) {
    int e = blockIdx.x * blockDim.x + threadIdx.x;
    if (e < EE) {
        int d = ei[EE + e];
        int s = ei[e];
        int pos = g_rowptr[d] + atomicAdd(&g_cnt[d], 1);
        float coef = g_dis[s] * ew[e] * g_dis[d];
        g_edge[pos] = ((ull)__float_as_uint(coef) << 32) | (unsigned)s;
    }
}

// ---------------- weight prepack -> mma fragment order ----------------
__global__ void prep_w_kernel(const float* __restrict__ w0, const float* __restrict__ w1,
                              const float* __restrict__ w2, const float* __restrict__ w3) {
    int v = blockIdx.x * 256 + threadIdx.x;
    if (v >= 21504) return;
    const float* w; int C, off;
    if (v < 3072)       { w = w0; C = 32; off = 0; }
    else if (v < 9216)  { w = w1; C = 64; off = 3072; }
    else if (v < 15360) { w = w2; C = 64; off = 9216; }
    else                { w = w3; C = 64; off = 15360; }
    int r = v - off;
    int KS = C / 16;
    int lane = r & 31; r >>= 5;
    int wid = r & 7;  r >>= 3;
    int ks = r % KS;  r /= KS;
    int tap = r % 3;  r /= 3;
    int s = r;
    u32 o4[4];
#pragma unroll
    for (int rr = 0; rr < 4; rr++) {
        float vv[2];
#pragma unroll
        for (int b = 0; b < 2; b++) {
            int m_local = (rr & 1) * 8 + (lane >> 2);
            int k = (rr >> 1) * 8 + (lane & 3) * 2 + b;
            int hh = wid * 8 + (m_local & 7);
            int orig = (m_local < 8) ? hh : 64 + hh;
            int c = ks * 16 + k;
            float val = w[(size_t)orig * C * 3 + c * 3 + tap];
            float hi = __bfloat162float(__float2bfloat16(val));
            vv[b] = (s == 0) ? hi : (val - hi);
        }
        o4[rr] = pack_bf2(vv[0], vv[1]);
    }
    ((uint4*)g_wfrag)[v] = make_uint4(o4[0], o4[1], o4[2], o4[3]);
}

// ---------------- input transpose + split: [n][32][12] -> hi/lo [n][12][32] ----
__global__ void transpose_x_kernel(const float* __restrict__ in,
                                   __nv_bfloat16* __restrict__ oh,
                                   __nv_bfloat16* __restrict__ ol) {
    int i = blockIdx.x * 256 + threadIdx.x;
    if (i < NN * 384) {
        int c = i & 31;
        int t = (i >> 5) % 12;
        int n = i / 384;
        float v = in[n * 384 + c * 12 + t];
        __nv_bfloat16 h = __float2bfloat16(v);
        oh[i] = h;
        ol[i] = __float2bfloat16(v - __bfloat162float(h));
    }
}

// ---------------- tensor-core gated temporal conv, cp.async double-buffered ----
// xh/xl: bf16 [col][C]; out fp32 [col][64] or hi/lo bf16
template <int C, bool OUTBF>
__global__ void __launch_bounds__(256, 2)
tconv_mma_kernel(const __nv_bfloat16* __restrict__ xh, const __nv_bfloat16* __restrict__ xl,
                 const uint4* __restrict__ wf, const float* __restrict__ bias,
                 float* __restrict__ outf,
                 __nv_bfloat16* __restrict__ oh, __nv_bfloat16* __restrict__ ol) {
    const int KS = C / 16;
    const int PAIRS = KS / 2;
    const int WST = C + 8;                 // smem row stride (bf16)
    const int BUFSZ = 132 * WST;           // one buffer, bf16 elems
    const int CHK = C / 8;                 // 16B chunks per row
    const int NCH = 66 * CHK;
    extern __shared__ __align__(16) __nv_bfloat16 sw[];
    const int tid = threadIdx.x;
    const int lane = tid & 31, wid = tid >> 5;
    u32 sb = smem_u32(sw);

    float bP = bias[wid * 8 + (lane >> 2)];
    float bQ = bias[64 + wid * 8 + (lane >> 2)];
    const int h = wid * 8 + (lane >> 2);
    const int lc = lane & 3;
    const int lq = lane >> 2;
    const int NT = TOTC / 64;

    // stage one tile's hi+lo window into buffer bufsel via cp.async
    auto stage = [&](int t, int bufsel) {
        int base = t * 64;
        for (int i = tid; i < 2 * NCH; i += 256) {
            int img = (i >= NCH);
            int j = i - img * NCH;
            int row = j / CHK, ch = j - row * CHK;
            int col = base - 1 + row;
            bool valid = (col >= 0 && col < TOTC);
            size_t cc = valid ? (size_t)col : 0;
            const __nv_bfloat16* src = (img ? xl : xh) + cc * C + ch * 8;
            u32 dst = sb + (u32)((bufsel * BUFSZ + (img * 66 + row) * WST) * 2 + ch * 16);
            cp_async16(dst, src, valid);
        }
    };

    int t0 = blockIdx.x;
    if (t0 < NT) stage(t0, 0);
    CP_COMMIT();
    int sel = 0;

    for (int tile = t0; tile < NT; tile += gridDim.x) {
        int base = tile * 64;
        int nxt = tile + gridDim.x;
        if (nxt < NT) {
            stage(nxt, sel ^ 1);
            CP_COMMIT();
            CP_WAIT1();
        } else {
            CP_WAIT0();
        }
        __syncthreads();

        // per-column boundary masks
        int m0[8], m2[8];
#pragma unroll
        for (int ns = 0; ns < 8; ns++) {
            int tm = (base + ns * 8 + lq) % 12;
            m0[ns] = (tm == 0);
            m2[ns] = (tm == 11);
        }

        float d[8][4];
#pragma unroll
        for (int ns = 0; ns < 8; ns++) { d[ns][0] = d[ns][1] = d[ns][2] = d[ns][3] = 0.f; }

        u32 bufbase = sb + (u32)(sel * BUFSZ * 2);

#pragma unroll
        for (int pair = 0; pair < PAIRS; pair++) {
            uint4 AH[3][2], AL[3][2];
#pragma unroll
            for (int tap = 0; tap < 3; tap++)
#pragma unroll
                for (int k2 = 0; k2 < 2; k2++) {
                    AH[tap][k2] = wf[((tap * KS + pair * 2 + k2) * 8 + wid) * 32 + lane];
                    AL[tap][k2] = wf[(((3 + tap) * KS + pair * 2 + k2) * 8 + wid) * 32 + lane];
                }
#pragma unroll
            for (int ns = 0; ns < 8; ns++) {
#pragma unroll
                for (int tap = 0; tap < 3; tap++) {
                    int row = ns * 8 + tap + (lane & 7);
                    int kk = pair * 32 + ((lane >> 3) & 3) * 8;
                    u32 a = bufbase + (u32)((row * WST + kk) * 2);
                    u32 b0, b1, b2, b3, l0, l1, l2, l3;
                    ldsm_x4(b0, b1, b2, b3, a);
                    ldsm_x4(l0, l1, l2, l3, a + (u32)(66 * WST * 2));
                    if (tap == 0 && m0[ns]) { b0 = b1 = b2 = b3 = l0 = l1 = l2 = l3 = 0u; }
                    if (tap == 2 && m2[ns]) { b0 = b1 = b2 = b3 = l0 = l1 = l2 = l3 = 0u; }
                    mma16816(d[ns][0], d[ns][1], d[ns][2], d[ns][3],
                             AH[tap][0].x, AH[tap][0].y, AH[tap][0].z, AH[tap][0].w, b0, b1);
                    mma16816(d[ns][0], d[ns][1], d[ns][2], d[ns][3],
                             AH[tap][0].x, AH[tap][0].y, AH[tap][0].z, AH[tap][0].w, l0, l1);
                    mma16816(d[ns][0], d[ns][1], d[ns][2], d[ns][3],
                             AL[tap][0].x, AL[tap][0].y, AL[tap][0].z, AL[tap][0].w, b0, b1);
                    mma16816(d[ns][0], d[ns][1], d[ns][2], d[ns][3],
                             AH[tap][1].x, AH[tap][1].y, AH[tap][1].z, AH[tap][1].w, b2, b3);
                    mma16816(d[ns][0], d[ns][1], d[ns][2], d[ns][3],
                             AH[tap][1].x, AH[tap][1].y, AH[tap][1].z, AH[tap][1].w, l2, l3);
                    mma16816(d[ns][0], d[ns][1], d[ns][2], d[ns][3],
                             AL[tap][1].x, AL[tap][1].y, AL[tap][1].z, AL[tap][1].w, b2, b3);
                }
            }
        }

        // ---- epilogue: gate in-register ----
#pragma unroll
        for (int ns = 0; ns < 8; ns++) {
            int col0 = base + ns * 8 + 2 * lc;
            float s2 = 1.f / (1.f + __expf(-(d[ns][2] + bQ)));
            float s3 = 1.f / (1.f + __expf(-(d[ns][3] + bQ)));
            float v0 = (d[ns][0] + bP) * s2;
            float v1 = (d[ns][1] + bP) * s3;
            if (OUTBF) {
                __nv_bfloat16 h0 = __float2bfloat16(v0);
                __nv_bfloat16 h1 = __float2bfloat16(v1);
                oh[(size_t)col0 * 64 + h] = h0;
                ol[(size_t)col0 * 64 + h] = __float2bfloat16(v0 - __bfloat162float(h0));
                oh[(size_t)(col0 + 1) * 64 + h] = h1;
                ol[(size_t)(col0 + 1) * 64 + h] = __float2bfloat16(v1 - __bfloat162float(h1));
            } else {
                outf[(size_t)col0 * 64 + h]       = v0;
                outf[(size_t)(col0 + 1) * 64 + h] = v1;
            }
        }
        __syncthreads();
        sel ^= 1;
    }
}

// ---------------- fused GCN (layout [n][t][c]), bf16 hi/lo output ----------------
__global__ void __launch_bounds__(192)
gcn_fused_kernel(const float* __restrict__ in,
                 __nv_bfloat16* __restrict__ oh, __nv_bfloat16* __restrict__ ol,
                 const float* __restrict__ W, const float* __restrict__ bias) {
    __shared__ __align__(16) float xs[768];
    __shared__ float Ws[64 * 65];
    int n = blockIdx.x, tid = threadIdx.x;

    for (int gi = tid; gi < 4096; gi += 192) {
        int o = gi >> 6, c = gi & 63;
        Ws[c * 65 + o] = W[gi];
    }

    float d = g_dis[n];
    float d2 = d * d;
    float4 acc = ((const float4*)(in + (size_t)n * FEAT))[tid];
    acc.x *= d2; acc.y *= d2; acc.z *= d2; acc.w *= d2;

    int e = g_rowptr[n], e1 = g_rowptr[n + 1];
    for (; e + 4 <= e1; e += 4) {
        ull p0 = g_edge[e], p1 = g_edge[e + 1], p2 = g_edge[e + 2], p3 = g_edge[e + 3];
        int s0 = (int)(unsigned)p0, s1 = (int)(unsigned)p1;
        int s2 = (int)(unsigned)p2, s3 = (int)(unsigned)p3;
        float c0 = __uint_as_float((unsigned)(p0 >> 32));
        float c1 = __uint_as_float((unsigned)(p1 >> 32));
        float c2 = __uint_as_float((unsigned)(p2 >> 32));
        float c3 = __uint_as_float((unsigned)(p3 >> 32));
        float4 v0 = ((const float4*)(in + (size_t)s0 * FEAT))[tid];
        float4 v1 = ((const float4*)(in + (size_t)s1 * FEAT))[tid];
        float4 v2 = ((const float4*)(in + (size_t)s2 * FEAT))[tid];
        float4 v3 = ((const float4*)(in + (size_t)s3 * FEAT))[tid];
        acc.x += c0 * v0.x + c1 * v1.x + c2 * v2.x + c3 * v3.x;
        acc.y += c0 * v0.y + c1 * v1.y + c2 * v2.y + c3 * v3.y;
        acc.z += c0 * v0.z + c1 * v1.z + c2 * v2.z + c3 * v3.z;
        acc.w += c0 * v0.w + c1 * v1.w + c2 * v2.w + c3 * v3.w;
    }
    for (; e < e1; e++) {
        ull p = g_edge[e];
        int s = (int)(unsigned)p;
        float cf = __uint_as_float((unsigned)(p >> 32));
        float4 v = ((const float4*)(in + (size_t)s * FEAT))[tid];
        acc.x += cf * v.x; acc.y += cf * v.y; acc.z += cf * v.z; acc.w += cf * v.w;
    }
    ((float4*)xs)[tid] = acc;
    __syncthreads();

    int o = tid & 63, tg = tid >> 6;
    float a0 = 0.f, a1 = 0.f, a2 = 0.f, a3 = 0.f;
#pragma unroll 8
    for (int c = 0; c < 64; c++) {
        float wv = Ws[c * 65 + o];
        const float* xp = xs + c;
        a0 += wv * xp[(tg * 4 + 0) * 64];
        a1 += wv * xp[(tg * 4 + 1) * 64];
        a2 += wv * xp[(tg * 4 + 2) * 64];
        a3 += wv * xp[(tg * 4 + 3) * 64];
    }
    float bv = bias[o];
    float rr[4] = {fmaxf(a0 + bv, 0.f), fmaxf(a1 + bv, 0.f),
                   fmaxf(a2 + bv, 0.f), fmaxf(a3 + bv, 0.f)};
#pragma unroll
    for (int i = 0; i < 4; i++) {
        size_t idx = (size_t)n * FEAT + (size_t)(tg * 4 + i) * 64 + o;
        __nv_bfloat16 hv = __float2bfloat16(rr[i]);
        oh[idx] = hv;
        ol[idx] = __float2bfloat16(rr[i] - __bfloat162float(hv));
    }
}

// ---------------- final conv (layout [n][t][c]) ----------------
__global__ void fin_kernel(const float* __restrict__ in, const float* __restrict__ w,
                           const float* __restrict__ b, float* __restrict__ out) {
    extern __shared__ float smf[];
    float* wt = smf;              // 12 rows, stride 772, reindexed [t*64+h]
    float* xt = smf + 12 * 772;   // 16 nodes, stride 772
    int tid = threadIdx.x;        // 192
    for (int i = tid; i < 12 * 768; i += 192) {
        int o = i / 768, r = i - o * 768;
        int t = r >> 6, hh = r & 63;
        wt[o * 772 + r] = w[o * 768 + hh * 12 + t];
    }
    int n0 = blockIdx.x * 16;
    for (int gi = tid; gi < 16 * 192; gi += 192) {
        int node = gi / 192, j = gi - node * 192;
        ((float4*)(xt + node * 772))[j] =
            ((const float4*)(in + (size_t)(n0 + node) * FEAT))[j];
    }
    __syncthreads();
    int node = tid / 12, o = tid - node * 12;
    const float* wr = wt + o * 772;
    const float* xr = xt + node * 772;
    float acc = 0.f;
#pragma unroll 4
    for (int j = 0; j < 192; j++) {
        float4 a = ((const float4*)wr)[j];
        float4 v = ((const float4*)xr)[j];
        acc += a.x * v.x + a.y * v.y + a.z * v.z + a.w * v.w;
    }
    out[(size_t)(n0 + node) * 12 + o] = acc + b[o];
}

// ---------------- launch ----------------
extern "C" void kernel_launch(void* const* d_in, const int* in_sizes, int n_in,
                              void* d_out, int out_size) {
    const float* x      = (const float*)d_in[0];
    const int*   ei     = (const int*)d_in[1];
    const float* ew     = (const float*)d_in[2];
    const float* tc1a_w = (const float*)d_in[3];
    const float* tc1a_b = (const float*)d_in[4];
    const float* gc1_w  = (const float*)d_in[5];
    const float* gc1_b  = (const float*)d_in[6];
    const float* tc1b_w = (const float*)d_in[7];
    const float* tc1b_b = (const float*)d_in[8];
    const float* tc2a_w = (const float*)d_in[9];
    const float* tc2a_b = (const float*)d_in[10];
    const float* gc2_w  = (const float*)d_in[11];
    const float* gc2_b  = (const float*)d_in[12];
    const float* tc2b_w = (const float*)d_in[13];
    const float* tc2b_b = (const float*)d_in[14];
    const float* fin_w  = (const float*)d_in[15];
    const float* fin_b  = (const float*)d_in[16];
    float* out = (float*)d_out;

    float *pA, *pB; uint4* pW;
    __nv_bfloat16 *pH1, *pL1, *pH2, *pL2;
    cudaGetSymbolAddress((void**)&pA, g_bufA);
    cudaGetSymbolAddress((void**)&pB, g_bufB);
    cudaGetSymbolAddress((void**)&pW, g_wfrag);
    cudaGetSymbolAddress((void**)&pH1, g_h1);
    cudaGetSymbolAddress((void**)&pL1, g_l1);
    cudaGetSymbolAddress((void**)&pH2, g_h2);
    cudaGetSymbolAddress((void**)&pL2, g_l2);

    const int smem32 = 2 * 132 * 40 * 2;    // 21120
    const int smem64 = 2 * 132 * 72 * 2;    // 38016
    const int smemF  = (12 + 16) * 772 * 4;
    cudaFuncSetAttribute(fin_kernel, cudaFuncAttributeMaxDynamicSharedMemorySize, smemF);
    cudaFuncSetAttribute((const void*)tconv_mma_kernel<64, true>,
                         cudaFuncAttributeMaxDynamicSharedMemorySize, smem64);
    cudaFuncSetAttribute((const void*)tconv_mma_kernel<64, false>,
                         cudaFuncAttributeMaxDynamicSharedMemorySize, smem64);
    cudaFuncSetAttribute((const void*)tconv_mma_kernel<32, false>,
                         cudaFuncAttributeMaxDynamicSharedMemorySize, smem32);

    // order: big mma kernel in ncu capture slot (#4)
    zero_kernel<<<(NN + 255) / 256, 256>>>();
    prep_w_kernel<<<(21504 + 255) / 256, 256>>>(tc1a_w, tc1b_w, tc2a_w, tc2b_w);
    transpose_x_kernel<<<(NN * 384 + 255) / 256, 256>>>(x, pH1, pL1);
    // tc1a: (H1,L1) -> A fp32
    tconv_mma_kernel<32, false><<<296, 256, smem32>>>(pH1, pL1, pW, tc1a_b, pA, 0, 0);
    hist_kernel<<<(EE + 255) / 256, 256>>>(ei, ew);
    scan_kernel<<<1, 1024>>>();
    scatter_kernel<<<(EE + 255) / 256, 256>>>(ei, ew);
    // gcn1: A -> (H1,L1)
    gcn_fused_kernel<<<NN, 192>>>(pA, pH1, pL1, gc1_w, gc1_b);
    // tc1b: (H1,L1) -> (H2,L2)
    tconv_mma_kernel<64, true><<<296, 256, smem64>>>(pH1, pL1, pW + 3072, tc1b_b, 0, pH2, pL2);
    // tc2a: (H2,L2) -> A fp32
    tconv_mma_kernel<64, false><<<296, 256, smem64>>>(pH2, pL2, pW + 9216, tc2a_b, pA, 0, 0);
    // gcn2: A -> (H1,L1)
    gcn_fused_kernel<<<NN, 192>>>(pA, pH1, pL1, gc2_w, gc2_b);
    // tc2b: (H1,L1) -> B fp32
    tconv_mma_kernel<64, false><<<296, 256, smem64>>>(pH1, pL1, pW + 15360, tc2b_b, pB, 0, 0);
    // fin: B -> out
    fin_kernel<<<NN / 16, 192, smemF>>>(pB, fin_w, fin_b, out);
}